// round 13
// baseline (speedup 1.0000x reference)
#include <cuda_runtime.h>
#include <cuda_bf16.h>
#include <cstdint>

#define BB  8
#define NN  4096
#define SS  1024
#define CIN 64
#define NC  (BB*SS)          /* 8192 centers */
#define NPTS (BB*NN)         /* 32768 points */

#define OUT_X_ELEMS   (NC*640)
#define OUT_POS_OFF   OUT_X_ELEMS
#define OUT_BATCH_OFF (OUT_X_ELEMS + NC*3)

#define INF_F __int_as_float(0x7f800000)

typedef unsigned short ushort_t;

// ---------------- scratch (__device__ globals: allocation-free contract) ---------
__device__ float    g_centers[NC*3];
__device__ int      g_nbr[NC*112];              // per-scale: K=16,32,64
__device__ int      g_cnt[3*NC];
__device__ float    g_xw[(size_t)NPTS*320];     // x@Wx + b (fp32), all 3 scales
__device__ ushort_t g_h1[218103808];            // h1 planes, all scales (436 MB)
__device__ ushort_t g_h2[218103808];            // h2 planes, all scales (436 MB)
__device__ ushort_t g_xpl[(size_t)2*NPTS*64];   // x planes
__device__ ushort_t g_wpl[1<<19];               // weight planes (transposed)

// ------------------------- helpers ----------------------------------------------
__device__ __forceinline__ void split_bf16(float v, ushort_t& h, ushort_t& l) {
    __nv_bfloat16 hb = __float2bfloat16(v);
    float r = v - __bfloat162float(hb);
    h = __bfloat16_as_ushort(hb);
    l = __bfloat16_as_ushort(__float2bfloat16(r));
}
__device__ __forceinline__ void mma16816(float* c, const uint32_t* a, const uint32_t* b) {
    asm volatile("mma.sync.aligned.m16n8k16.row.col.f32.bf16.bf16.f32 "
                 "{%0,%1,%2,%3}, {%4,%5,%6,%7}, {%8,%9}, {%0,%1,%2,%3};"
                 : "+f"(c[0]), "+f"(c[1]), "+f"(c[2]), "+f"(c[3])
                 : "r"(a[0]), "r"(a[1]), "r"(a[2]), "r"(a[3]),
                   "r"(b[0]), "r"(b[1]));
}
__device__ __forceinline__ uint32_t smem_u32(const void* p) {
    uint32_t a;
    asm("{ .reg .u64 t; cvta.to.shared.u64 t, %1; cvt.u32.u64 %0, t; }" : "=r"(a) : "l"(p));
    return a;
}
__device__ __forceinline__ void cpa16(uint32_t dst, const void* src) {
    asm volatile("cp.async.cg.shared.global [%0], [%1], 16;" :: "r"(dst), "l"(src) : "memory");
}
#define CP_COMMIT() asm volatile("cp.async.commit_group;" ::: "memory")
#define CP_WAIT0()  asm volatile("cp.async.wait_group 0;" ::: "memory")
#define CP_WAIT1()  asm volatile("cp.async.wait_group 1;" ::: "memory")
#define LDSM4(r0,r1,r2,r3,addr) \
    asm volatile("ldmatrix.sync.aligned.m8n8.x4.shared.b16 {%0,%1,%2,%3}, [%4];" \
                 : "=r"(r0), "=r"(r1), "=r"(r2), "=r"(r3) : "r"(addr))

// ============================ conversion kernels =================================
__global__ void xconv(const float* __restrict__ x, ushort_t* __restrict__ hi,
                      ushort_t* __restrict__ lo)
{
    size_t idx = (size_t)blockIdx.x * 256 + threadIdx.x;
    if (idx >= (size_t)NPTS * 64) return;
    ushort_t h, l; split_bf16(x[idx], h, l);
    hi[idx] = h; lo[idx] = l;
}
__global__ void wconv(const float* __restrict__ W, int Nc, int k0, int KC, int N,
                      ushort_t* __restrict__ hi, ushort_t* __restrict__ lo)
{
    int idx = blockIdx.x * 256 + threadIdx.x;
    if (idx >= N * KC) return;
    int n = idx / KC, k = idx % KC;
    ushort_t h, l; split_bf16(W[(size_t)(k0 + k) * Nc + n], h, l);
    hi[idx] = h; lo[idx] = l;
}

// =================================================================================
// Planar bf16 double-split GEMM: cp.async double buffering + ldmatrix frag loads.
// MODE 0: fp32 out, no relu. MODE 1: hi/lo plane out (+relu).
// =================================================================================
template<int KC, int BN, int MODE>
__global__ void __launch_bounds__(256, 2) hgemm_pl(
    const ushort_t* __restrict__ aHi, const ushort_t* __restrict__ aLo,
    const ushort_t* __restrict__ bHi, const ushort_t* __restrict__ bLo,
    const float* __restrict__ bias,
    float* __restrict__ Cf, ushort_t* __restrict__ coHi, ushort_t* __restrict__ coLo,
    int Nc)
{
    extern __shared__ char dsm[];
    constexpr int KP = 40;
    float* s_bias = (float*)(dsm + 2*(128+BN)*KP*2*2);

    const uint32_t base   = smem_u32(dsm);
    const uint32_t AL_OFF = (uint32_t)(2*128*KP*2);
    const uint32_t BH_OFF = AL_OFF * 2;
    const uint32_t BL_OFF = BH_OFF + (uint32_t)(2*BN*KP*2);

    const int tid  = threadIdx.x;
    const int row0 = blockIdx.x * 128;
    const int col0 = blockIdx.y * BN;
    if (tid < BN) s_bias[tid] = bias[col0 + tid];

    const int lane = tid & 31, w = tid >> 5;
    const int wm = w & 3, wn = w >> 2;
    constexpr int WN  = BN / 2;
    constexpr int NTL = WN / 8;

    float acc[2][NTL][4];
#pragma unroll
    for (int mt = 0; mt < 2; mt++)
#pragma unroll
        for (int nt = 0; nt < NTL; nt++)
#pragma unroll
            for (int q = 0; q < 4; q++) acc[mt][nt][q] = 0.f;

    constexpr int NKB = KC / 32;

    auto load_stage = [&](int kb, int buf) {
        const int kk = kb * 32;
#pragma unroll
        for (int i = 0; i < 2; i++) {
            int c = tid * 2 + i;
            int row = c >> 2, kc = (c & 3) * 8;
            const ushort_t* s1 = aHi + (size_t)(row0 + row) * KC + kk + kc;
            const ushort_t* s2 = aLo + (size_t)(row0 + row) * KC + kk + kc;
            uint32_t d = base + (uint32_t)((buf * 128 * KP + row * KP + kc) * 2);
            cpa16(d, s1);
            cpa16(d + AL_OFF, s2);
        }
        if (BN == 128) {
#pragma unroll
            for (int i = 0; i < 2; i++) {
                int c = tid * 2 + i;
                int row = c >> 2, kc = (c & 3) * 8;
                const ushort_t* s1 = bHi + (size_t)(col0 + row) * KC + kk + kc;
                const ushort_t* s2 = bLo + (size_t)(col0 + row) * KC + kk + kc;
                uint32_t d = base + BH_OFF + (uint32_t)((buf * BN * KP + row * KP + kc) * 2);
                cpa16(d, s1);
                cpa16(d + (BL_OFF - BH_OFF), s2);
            }
        } else {
            int c = tid;
            int row = c >> 2, kc = (c & 3) * 8;
            const ushort_t* s1 = bHi + (size_t)(col0 + row) * KC + kk + kc;
            const ushort_t* s2 = bLo + (size_t)(col0 + row) * KC + kk + kc;
            uint32_t d = base + BH_OFF + (uint32_t)((buf * BN * KP + row * KP + kc) * 2);
            cpa16(d, s1);
            cpa16(d + (BL_OFF - BH_OFF), s2);
        }
    };

    const int g  = lane >> 3, lr = lane & 7;
    int aoff0[2], boff0[NTL/2];
#pragma unroll
    for (int mt = 0; mt < 2; mt++)
        aoff0[mt] = (wm*32 + mt*16 + (g & 1)*8 + lr) * KP + (g >> 1)*8;
#pragma unroll
    for (int p = 0; p < NTL/2; p++)
        boff0[p] = (wn*WN + p*16 + (g >> 1)*8 + lr) * KP + (g & 1)*8;

    load_stage(0, 0);
    CP_COMMIT();

    int buf = 0;
    for (int kb = 0; kb < NKB; kb++) {
        if (kb + 1 < NKB) { load_stage(kb + 1, buf ^ 1); CP_COMMIT(); CP_WAIT1(); }
        else              { CP_WAIT0(); }
        __syncthreads();

        const uint32_t aBuf = base + (uint32_t)(buf*128*KP*2);
        const uint32_t bBuf = base + BH_OFF + (uint32_t)(buf*BN*KP*2);
#pragma unroll
        for (int k2 = 0; k2 < 32; k2 += 16) {
            uint32_t ah[2][4], al[2][4];
#pragma unroll
            for (int mt = 0; mt < 2; mt++) {
                uint32_t ad = aBuf + (uint32_t)((aoff0[mt] + k2) * 2);
                LDSM4(ah[mt][0], ah[mt][1], ah[mt][2], ah[mt][3], ad);
                LDSM4(al[mt][0], al[mt][1], al[mt][2], al[mt][3], ad + AL_OFF);
            }
            uint32_t bh[NTL][2], bl[NTL][2];
#pragma unroll
            for (int p = 0; p < NTL/2; p++) {
                uint32_t bd = bBuf + (uint32_t)((boff0[p] + k2) * 2);
                LDSM4(bh[2*p][0], bh[2*p][1], bh[2*p+1][0], bh[2*p+1][1], bd);
                LDSM4(bl[2*p][0], bl[2*p][1], bl[2*p+1][0], bl[2*p+1][1],
                      bd + (BL_OFF - BH_OFF));
            }
#pragma unroll
            for (int nt = 0; nt < NTL; nt++)
#pragma unroll
                for (int mt = 0; mt < 2; mt++) {
                    mma16816(acc[mt][nt], ah[mt], bh[nt]);
                    mma16816(acc[mt][nt], ah[mt], bl[nt]);
                    mma16816(acc[mt][nt], al[mt], bh[nt]);
                }
        }
        __syncthreads();
        buf ^= 1;
    }

#pragma unroll
    for (int mt = 0; mt < 2; mt++) {
        int r0 = row0 + wm*32 + mt*16 + (lane>>2);
#pragma unroll
        for (int nt = 0; nt < NTL; nt++) {
            int cc = wn*WN + nt*8 + (lane&3)*2;
            float b0 = s_bias[cc], b1 = s_bias[cc+1];
            float v0 = acc[mt][nt][0] + b0, v1 = acc[mt][nt][1] + b1;
            float v2 = acc[mt][nt][2] + b0, v3 = acc[mt][nt][3] + b1;
            if (MODE == 0) {
                *(float2*)&Cf[(size_t)r0 * Nc + col0 + cc]     = make_float2(v0, v1);
                *(float2*)&Cf[(size_t)(r0+8) * Nc + col0 + cc] = make_float2(v2, v3);
            } else {
                v0 = fmaxf(v0, 0.f); v1 = fmaxf(v1, 0.f);
                v2 = fmaxf(v2, 0.f); v3 = fmaxf(v3, 0.f);
                ushort_t h0,l0,h1,l1;
                split_bf16(v0,h0,l0); split_bf16(v1,h1,l1);
                *(uint32_t*)&coHi[(size_t)r0 * Nc + col0 + cc] = (uint32_t)h0 | ((uint32_t)h1<<16);
                *(uint32_t*)&coLo[(size_t)r0 * Nc + col0 + cc] = (uint32_t)l0 | ((uint32_t)l1<<16);
                split_bf16(v2,h0,l0); split_bf16(v3,h1,l1);
                *(uint32_t*)&coHi[(size_t)(r0+8) * Nc + col0 + cc] = (uint32_t)h0 | ((uint32_t)h1<<16);
                *(uint32_t*)&coLo[(size_t)(r0+8) * Nc + col0 + cc] = (uint32_t)l0 | ((uint32_t)l1<<16);
            }
        }
    }
}

// =================================================================================
// Planar GEMM + bias + relu + masked segment-max epilogue (last layer).
// =================================================================================
template<int KC, int BN>
__global__ void __launch_bounds__(256, 2) hmax_pl(
    const ushort_t* __restrict__ aHi, const ushort_t* __restrict__ aLo,
    const ushort_t* __restrict__ bHi, const ushort_t* __restrict__ bLo,
    const float* __restrict__ bias, const int* __restrict__ cnt,
    float* __restrict__ out, int Nc, int Kn, int colOff)
{
    extern __shared__ char dsm[];
    constexpr int KP = 40;
    float* s_bias = (float*)(dsm + 2*(128+BN)*KP*2*2);
    float* red    = (float*)dsm;

    const uint32_t base   = smem_u32(dsm);
    const uint32_t AL_OFF = (uint32_t)(2*128*KP*2);
    const uint32_t BH_OFF = AL_OFF * 2;
    const uint32_t BL_OFF = BH_OFF + (uint32_t)(2*BN*KP*2);

    const int tid  = threadIdx.x;
    const int row0 = blockIdx.x * 128;
    const int col0 = blockIdx.y * BN;
    if (tid < BN) s_bias[tid] = bias[col0 + tid];

    const int lane = tid & 31, w = tid >> 5;
    const int wm = w & 3, wn = w >> 2;
    constexpr int WN  = BN / 2;
    constexpr int NTL = WN / 8;

    float acc[2][NTL][4];
#pragma unroll
    for (int mt = 0; mt < 2; mt++)
#pragma unroll
        for (int nt = 0; nt < NTL; nt++)
#pragma unroll
            for (int q = 0; q < 4; q++) acc[mt][nt][q] = 0.f;

    constexpr int NKB = KC / 32;

    auto load_stage = [&](int kb, int buf) {
        const int kk = kb * 32;
#pragma unroll
        for (int i = 0; i < 2; i++) {
            int c = tid * 2 + i;
            int row = c >> 2, kc = (c & 3) * 8;
            const ushort_t* s1 = aHi + (size_t)(row0 + row) * KC + kk + kc;
            const ushort_t* s2 = aLo + (size_t)(row0 + row) * KC + kk + kc;
            uint32_t d = base + (uint32_t)((buf * 128 * KP + row * KP + kc) * 2);
            cpa16(d, s1);
            cpa16(d + AL_OFF, s2);
        }
#pragma unroll
        for (int i = 0; i < 2; i++) {
            int c = tid * 2 + i;
            int row = c >> 2, kc = (c & 3) * 8;
            const ushort_t* s1 = bHi + (size_t)(col0 + row) * KC + kk + kc;
            const ushort_t* s2 = bLo + (size_t)(col0 + row) * KC + kk + kc;
            uint32_t d = base + BH_OFF + (uint32_t)((buf * BN * KP + row * KP + kc) * 2);
            cpa16(d, s1);
            cpa16(d + (BL_OFF - BH_OFF), s2);
        }
    };

    const int g  = lane >> 3, lr = lane & 7;
    int aoff0[2], boff0[NTL/2];
#pragma unroll
    for (int mt = 0; mt < 2; mt++)
        aoff0[mt] = (wm*32 + mt*16 + (g & 1)*8 + lr) * KP + (g >> 1)*8;
#pragma unroll
    for (int p = 0; p < NTL/2; p++)
        boff0[p] = (wn*WN + p*16 + (g >> 1)*8 + lr) * KP + (g & 1)*8;

    load_stage(0, 0);
    CP_COMMIT();

    int buf = 0;
    for (int kb = 0; kb < NKB; kb++) {
        if (kb + 1 < NKB) { load_stage(kb + 1, buf ^ 1); CP_COMMIT(); CP_WAIT1(); }
        else              { CP_WAIT0(); }
        __syncthreads();

        const uint32_t aBuf = base + (uint32_t)(buf*128*KP*2);
        const uint32_t bBuf = base + BH_OFF + (uint32_t)(buf*BN*KP*2);
#pragma unroll
        for (int k2 = 0; k2 < 32; k2 += 16) {
            uint32_t ah[2][4], al[2][4];
#pragma unroll
            for (int mt = 0; mt < 2; mt++) {
                uint32_t ad = aBuf + (uint32_t)((aoff0[mt] + k2) * 2);
                LDSM4(ah[mt][0], ah[mt][1], ah[mt][2], ah[mt][3], ad);
                LDSM4(al[mt][0], al[mt][1], al[mt][2], al[mt][3], ad + AL_OFF);
            }
            uint32_t bh[NTL][2], bl[NTL][2];
#pragma unroll
            for (int p = 0; p < NTL/2; p++) {
                uint32_t bd = bBuf + (uint32_t)((boff0[p] + k2) * 2);
                LDSM4(bh[2*p][0], bh[2*p][1], bh[2*p+1][0], bh[2*p+1][1], bd);
                LDSM4(bl[2*p][0], bl[2*p][1], bl[2*p+1][0], bl[2*p+1][1],
                      bd + (BL_OFF - BH_OFF));
            }
#pragma unroll
            for (int nt = 0; nt < NTL; nt++)
#pragma unroll
                for (int mt = 0; mt < 2; mt++) {
                    mma16816(acc[mt][nt], ah[mt], bh[nt]);
                    mma16816(acc[mt][nt], ah[mt], bl[nt]);
                    mma16816(acc[mt][nt], al[mt], bh[nt]);
                }
        }
        __syncthreads();
        buf ^= 1;
    }

#pragma unroll
    for (int mt = 0; mt < 2; mt++) {
        int lr2 = wm*32 + mt*16 + (lane>>2);
        int ok0 = (lr2 % Kn)     < cnt[(row0 + lr2) / Kn];
        int ok1 = ((lr2+8) % Kn) < cnt[(row0 + lr2 + 8) / Kn];
#pragma unroll
        for (int nt = 0; nt < NTL; nt++) {
            int cc = wn*WN + nt*8 + (lane&3)*2;
            float b0 = s_bias[cc], b1 = s_bias[cc+1];
            float v0 = fmaxf(acc[mt][nt][0] + b0, 0.f);
            float v1 = fmaxf(acc[mt][nt][1] + b1, 0.f);
            float v2 = fmaxf(acc[mt][nt][2] + b0, 0.f);
            float v3 = fmaxf(acc[mt][nt][3] + b1, 0.f);
            red[(size_t)lr2*(BN+1) + cc]         = ok0 ? v0 : -INF_F;
            red[(size_t)lr2*(BN+1) + cc + 1]     = ok0 ? v1 : -INF_F;
            red[(size_t)(lr2+8)*(BN+1) + cc]     = ok1 ? v2 : -INF_F;
            red[(size_t)(lr2+8)*(BN+1) + cc + 1] = ok1 ? v3 : -INF_F;
        }
    }
    __syncthreads();

    const int nseg = 128 / Kn;
    const int cb   = row0 / Kn;
    for (int o = tid; o < nseg * BN; o += 256) {
        int seg = o / BN, col = o % BN;
        float m = -INF_F;
        int rb = seg * Kn;
        for (int r = 0; r < Kn; r++)
            m = fmaxf(m, red[(size_t)(rb + r)*(BN+1) + col]);
        out[(size_t)(cb + seg) * 640 + colOff + col0 + col] = m;
    }
}

// =================================================================================
// 1) Farthest point sampling — single barrier/step, parity-double-buffered
//    reduction, all warps compute the final argmax. Distance math bitwise-frozen;
//    argmax selection (first-max, lowest index) identical to the 2-barrier version.
// =================================================================================
__global__ void __launch_bounds__(1024) fps_kernel(const float* __restrict__ pos)
{
    const int b    = blockIdx.x;
    const int tid  = threadIdx.x;
    const int lane = tid & 31, wid = tid >> 5;
    const float* p = pos + (size_t)b * NN * 3;

    __shared__ float s_xyz[NN*3];
    __shared__ float s_v[2][32];
    __shared__ int   s_i[2][32];

    for (int i = tid; i < NN*3; i += 1024) s_xyz[i] = p[i];

    float px[4], py[4], pz[4], md[4];
#pragma unroll
    for (int i = 0; i < 4; i++) {
        int j = tid * 4 + i;
        px[i] = p[j*3+0]; py[i] = p[j*3+1]; pz[i] = p[j*3+2];
        md[i] = INF_F;
    }

    float cx = p[0], cy = p[1], cz = p[2];
    if (tid == 0) {
        size_t o = (size_t)b * SS * 3;
        g_centers[o] = cx; g_centers[o+1] = cy; g_centers[o+2] = cz;
    }
    __syncthreads();

    int par = 0;
    for (int s = 1; s < SS; s++) {
        float bv = -1.0f; int bi = 0;
#pragma unroll
        for (int i = 0; i < 4; i++) {
            float dx = __fsub_rn(px[i], cx);
            float dy = __fsub_rn(py[i], cy);
            float dz = __fsub_rn(pz[i], cz);
            float d2 = __fadd_rn(__fadd_rn(__fmul_rn(dx,dx), __fmul_rn(dy,dy)),
                                 __fmul_rn(dz,dz));
            md[i] = fminf(md[i], d2);
            if (md[i] > bv) { bv = md[i]; bi = tid*4 + i; }
        }
        unsigned ubv  = __float_as_uint(bv);
        unsigned wmax = __reduce_max_sync(0xffffffffu, ubv);
        unsigned ball = __ballot_sync(0xffffffffu, ubv == wmax);
        int src = __ffs(ball) - 1;
        int wbi = __shfl_sync(0xffffffffu, bi, src);
        if (lane == 0) { s_v[par][wid] = __uint_as_float(wmax); s_i[par][wid] = wbi; }
        __syncthreads();

        // every warp computes the identical final 32-way argmax
        unsigned v  = __float_as_uint(s_v[par][lane]);
        int      iv = s_i[par][lane];
        unsigned m2 = __reduce_max_sync(0xffffffffu, v);
        unsigned ba = __ballot_sync(0xffffffffu, v == m2);
        int sc = __ffs(ba) - 1;
        int i2 = __shfl_sync(0xffffffffu, iv, sc);

        cx = s_xyz[i2*3+0]; cy = s_xyz[i2*3+1]; cz = s_xyz[i2*3+2];
        if (tid == 0) {
            size_t o = ((size_t)b*SS + s) * 3;
            g_centers[o] = cx; g_centers[o+1] = cy; g_centers[o+2] = cz;
        }
        par ^= 1;
    }
}

// =================================================================================
// 2) Radius ball query + exact top-K (per-scale output pointers)
// =================================================================================
__global__ void __launch_bounds__(256) nbr_kernel(const float* __restrict__ pos,
                                                  float r2, int Kn,
                                                  int* __restrict__ nbrOut,
                                                  int* __restrict__ cntOut)
{
    __shared__ unsigned long long keys[4096];
    __shared__ int s_count;
    const int ci  = blockIdx.x;
    const int b   = ci / SS;
    const int tid = threadIdx.x;
    if (tid == 0) s_count = 0;
    __syncthreads();

    const float cx = g_centers[ci*3+0], cy = g_centers[ci*3+1], cz = g_centers[ci*3+2];
    const float* p = pos + (size_t)b * NN * 3;

    for (int j = tid; j < NN; j += 256) {
        float dx = __fsub_rn(cx, p[j*3+0]);
        float dy = __fsub_rn(cy, p[j*3+1]);
        float dz = __fsub_rn(cz, p[j*3+2]);
        float d2 = __fadd_rn(__fadd_rn(__fmul_rn(dx,dx), __fmul_rn(dy,dy)),
                             __fmul_rn(dz,dz));
        if (d2 <= r2) {
            int w = atomicAdd(&s_count, 1);
            keys[w] = (((unsigned long long)__float_as_uint(d2)) << 32) | (unsigned)j;
        }
    }
    __syncthreads();
    const int M = s_count;
    int n = 16;
    while (n < M || n < Kn) n <<= 1;
    for (int i = M + tid; i < n; i += 256) keys[i] = 0xFFFFFFFFFFFFFFFFULL;
    __syncthreads();

    for (int size = 2; size <= n; size <<= 1) {
        for (int stride = size >> 1; stride > 0; stride >>= 1) {
            for (int i = tid; i < (n >> 1); i += 256) {
                int p0 = 2*i - (i & (stride - 1));
                int p1 = p0 + stride;
                unsigned long long a = keys[p0], c = keys[p1];
                bool asc = ((p0 & size) == 0);
                if (asc ? (a > c) : (a < c)) { keys[p0] = c; keys[p1] = a; }
            }
            __syncthreads();
        }
    }

    for (int k = tid; k < Kn; k += 256) {
        int j = (k < M) ? (int)(keys[k] & 0xFFFFFFFFu) : 0;
        nbrOut[(size_t)ci * Kn + k] = b * NN + j;
    }
    if (tid == 0) cntOut[ci] = (M < Kn) ? M : Kn;
}

// =================================================================================
// 3) Fused gather + layer-1 (emits h1 bf16 hi/lo planes; per-scale nbr pointer)
// =================================================================================
__global__ void __launch_bounds__(256) fused_l1(const float* __restrict__ pos,
                                                const float* __restrict__ xwb,
                                                const float* __restrict__ W1,
                                                int Kn, int c1,
                                                const int* __restrict__ nbr,
                                                ushort_t* __restrict__ hHi,
                                                ushort_t* __restrict__ hLo)
{
    __shared__ float s_wp[3*128];
    const int tid  = threadIdx.x;
    for (int i = tid; i < 3 * c1; i += 256)
        s_wp[i] = W1[(size_t)(64 + i / c1) * c1 + (i % c1)];
    __syncthreads();

    const int warp = tid >> 5, lane = tid & 31;
    const long row = (long)blockIdx.x * 8 + warp;
    const int  ci  = (int)(row / Kn);
    const int  j   = nbr[row];

    const float p0 = __fsub_rn(pos[(size_t)j*3+0], g_centers[(size_t)ci*3+0]);
    const float p1 = __fsub_rn(pos[(size_t)j*3+1], g_centers[(size_t)ci*3+1]);
    const float p2 = __fsub_rn(pos[(size_t)j*3+2], g_centers[(size_t)ci*3+2]);

    const float* xr = xwb + (size_t)j * c1;
    const size_t rb = (size_t)row * c1;
#pragma unroll 2
    for (int it = 0; it < c1/64; it++) {
        int cc = lane*2 + it*64;
        float v0 = xr[cc], v1 = xr[cc+1];
        v0 = fmaf(p0, s_wp[cc],          v0);
        v0 = fmaf(p1, s_wp[c1 + cc],     v0);
        v0 = fmaf(p2, s_wp[2*c1 + cc],   v0);
        v1 = fmaf(p0, s_wp[cc+1],        v1);
        v1 = fmaf(p1, s_wp[c1 + cc+1],   v1);
        v1 = fmaf(p2, s_wp[2*c1 + cc+1], v1);
        v0 = fmaxf(v0, 0.f); v1 = fmaxf(v1, 0.f);
        ushort_t h0,l0,h1,l1;
        split_bf16(v0,h0,l0); split_bf16(v1,h1,l1);
        *(uint32_t*)&hHi[rb + cc] = (uint32_t)h0 | ((uint32_t)h1<<16);
        *(uint32_t*)&hLo[rb + cc] = (uint32_t)l0 | ((uint32_t)l1<<16);
    }
}

// =================================================================================
// 4) new_pos / new_batch tail
// =================================================================================
__global__ void tail_kernel(float* __restrict__ out, int writePos, int writeBatch)
{
    int i = blockIdx.x * blockDim.x + threadIdx.x;
    if (i >= NC) return;
    if (writePos) {
        out[OUT_POS_OFF + i*3 + 0] = g_centers[i*3+0];
        out[OUT_POS_OFF + i*3 + 1] = g_centers[i*3+1];
        out[OUT_POS_OFF + i*3 + 2] = g_centers[i*3+2];
    }
    if (writeBatch) out[OUT_BATCH_OFF + i] = (float)(i / SS);
}

// =================================================================================
static inline int smem_pl(int BN) { return 320 * (128 + BN) + 512; }

extern "C" void kernel_launch(void* const* d_in, const int* in_sizes, int n_in,
                              void* d_out, int out_size)
{
    const float* x   = (const float*)d_in[0];
    const float* pos = (const float*)d_in[1];
    const float* W[3][3];
    const float* bv[3][3];
    int ii = 3;
    for (int s = 0; s < 3; s++)
        for (int l = 0; l < 3; l++) {
            W[s][l]  = (const float*)d_in[ii++];
            bv[s][l] = (const float*)d_in[ii++];
        }
    float* out = (float*)d_out;

    void *pX = nullptr, *pXP = nullptr, *pWP = nullptr, *pH1 = nullptr, *pH2 = nullptr;
    void *pNB = nullptr, *pCT = nullptr;
    cudaGetSymbolAddress(&pX, g_xw);
    cudaGetSymbolAddress(&pXP, g_xpl);
    cudaGetSymbolAddress(&pWP, g_wpl);
    cudaGetSymbolAddress(&pH1, g_h1);
    cudaGetSymbolAddress(&pH2, g_h2);
    cudaGetSymbolAddress(&pNB, g_nbr);
    cudaGetSymbolAddress(&pCT, g_cnt);
    float*    xw   = (float*)pX;
    ushort_t* xpl  = (ushort_t*)pXP;
    ushort_t* wpl  = (ushort_t*)pWP;
    ushort_t* h1b  = (ushort_t*)pH1;
    ushort_t* h2b  = (ushort_t*)pH2;
    int*      nbrb = (int*)pNB;
    int*      cntb = (int*)pCT;

    cudaFuncSetAttribute(hgemm_pl<64,64,0>,   cudaFuncAttributeMaxDynamicSharedMemorySize, smem_pl(64));
    cudaFuncSetAttribute(hgemm_pl<64,128,0>,  cudaFuncAttributeMaxDynamicSharedMemorySize, smem_pl(128));
    cudaFuncSetAttribute(hgemm_pl<64,64,1>,   cudaFuncAttributeMaxDynamicSharedMemorySize, smem_pl(64));
    cudaFuncSetAttribute(hgemm_pl<128,128,1>, cudaFuncAttributeMaxDynamicSharedMemorySize, smem_pl(128));
    cudaFuncSetAttribute(hmax_pl<64,128>,     cudaFuncAttributeMaxDynamicSharedMemorySize, smem_pl(128));
    cudaFuncSetAttribute(hmax_pl<128,128>,    cudaFuncAttributeMaxDynamicSharedMemorySize, smem_pl(128));

    const int    Kl[3]    = {16, 32, 64};
    const float  r2l[3]   = {(float)(0.1*0.1), (float)(0.2*0.2), (float)(0.4*0.4)};
    const int    c1[3]    = {64, 128, 128};
    const int    coff[3]  = {0, 128, 384};
    const size_t xwOff[3] = {0, (size_t)NPTS*64, (size_t)NPTS*(64+128)};
    const size_t E[3]  = {(size_t)NC*16*64, (size_t)NC*32*128, (size_t)NC*64*128};
    const size_t hO[3] = {0, 2*E[0], 2*E[0] + 2*E[1]};
    const size_t nbrOff[3] = {0, (size_t)NC*16, (size_t)NC*(16+32)};

    size_t woff = 0;
    size_t wxO[3], w2O[3], w3O[3], wxS[3], w2S[3], w3S[3];
    for (int s = 0; s < 3; s++) {
        wxS[s] = (size_t)64 * c1[s];    wxO[s] = woff; woff += 2*wxS[s];
        w2S[s] = (size_t)c1[s] * (s ? 128 : 64); w2O[s] = woff; woff += 2*w2S[s];
        w3S[s] = (size_t)(s ? 128 : 64) * (s ? 256 : 128); w3O[s] = woff; woff += 2*w3S[s];
    }

    // ---- 2-stream envelope (resource pattern that passed in R9/R12) ------------
    cudaStream_t s2;
    cudaStreamCreateWithFlags(&s2, cudaStreamNonBlocking);
    cudaEvent_t evFork, evCent, evXw0, evNbr2, evTail;
    cudaEventCreateWithFlags(&evFork, cudaEventDisableTiming);
    cudaEventCreateWithFlags(&evCent, cudaEventDisableTiming);
    cudaEventCreateWithFlags(&evXw0,  cudaEventDisableTiming);
    cudaEventCreateWithFlags(&evNbr2, cudaEventDisableTiming);
    cudaEventCreateWithFlags(&evTail, cudaEventDisableTiming);

    cudaEventRecord(evFork, 0);
    cudaStreamWaitEvent(s2, evFork, 0);

    // side stream: fps
    fps_kernel<<<BB, 1024, 0, s2>>>(pos);
    cudaEventRecord(evCent, s2);

    // main stream: conversions + xw GEMMs (scale-0 xw first, then record evXw0)
    xconv<<<(int)(((size_t)NPTS*64 + 255)/256), 256>>>(x, xpl, xpl + (size_t)NPTS*64);
    for (int s = 0; s < 3; s++) {
        const int c2v = s ? 128 : 64, c3v = s ? 256 : 128;
        wconv<<<(int)((wxS[s]+255)/256), 256>>>(W[s][0], c1[s], 0, 64, c1[s],
                                                wpl + wxO[s], wpl + wxO[s] + wxS[s]);
        wconv<<<(int)((w2S[s]+255)/256), 256>>>(W[s][1], c2v, 0, c1[s], c2v,
                                                wpl + w2O[s], wpl + w2O[s] + w2S[s]);
        wconv<<<(int)((w3S[s]+255)/256), 256>>>(W[s][2], c3v, 0, c2v, c3v,
                                                wpl + w3O[s], wpl + w3O[s] + w3S[s]);
    }
    hgemm_pl<64,64,0><<<dim3(NPTS/128,1), 256, smem_pl(64)>>>(
        xpl, xpl + (size_t)NPTS*64, wpl + wxO[0], wpl + wxO[0] + wxS[0],
        bv[0][0], xw + xwOff[0], nullptr, nullptr, 64);
    cudaEventRecord(evXw0, 0);
    hgemm_pl<64,128,0><<<dim3(NPTS/128,1), 256, smem_pl(128)>>>(
        xpl, xpl + (size_t)NPTS*64, wpl + wxO[1], wpl + wxO[1] + wxS[1],
        bv[1][0], xw + xwOff[1], nullptr, nullptr, 128);
    hgemm_pl<64,128,0><<<dim3(NPTS/128,1), 256, smem_pl(128)>>>(
        xpl, xpl + (size_t)NPTS*64, wpl + wxO[2], wpl + wxO[2] + wxS[2],
        bv[2][0], xw + xwOff[2], nullptr, nullptr, 128);

    // side stream: nbr0, nbr2 (both depend only on centers), then s0 chain + tail
    {
        const int K = Kl[0], R = NC * K;
        ushort_t* h1Hi = h1b + hO[0];
        ushort_t* h1Lo = h1Hi + E[0];
        ushort_t* h2Hi = h2b + hO[0];
        ushort_t* h2Lo = h2Hi + E[0];
        int* nbrS = nbrb + nbrOff[0];
        int* cntS = cntb;

        nbr_kernel<<<NC, 256, 0, s2>>>(pos, r2l[0], K, nbrS, cntS);
        nbr_kernel<<<NC, 256, 0, s2>>>(pos, r2l[2], Kl[2],
                                       nbrb + nbrOff[2], cntb + 2*NC);
        cudaEventRecord(evNbr2, s2);

        cudaStreamWaitEvent(s2, evXw0, 0);
        fused_l1<<<R/8, 256, 0, s2>>>(pos, xw + xwOff[0], W[0][0], K, c1[0],
                                      nbrS, h1Hi, h1Lo);
        hgemm_pl<64,64,1><<<dim3(R/128,1), 256, smem_pl(64), s2>>>(
            h1Hi, h1Lo, wpl + w2O[0], wpl + w2O[0] + w2S[0],
            bv[0][1], nullptr, h2Hi, h2Lo, 64);
        hmax_pl<64,128><<<dim3(R/128,1), 256, smem_pl(128), s2>>>(
            h2Hi, h2Lo, wpl + w3O[0], wpl + w3O[0] + w3S[0],
            bv[0][2], cntS, out, 128, K, coff[0]);
        const int writePos   = (out_size >= OUT_POS_OFF + NC*3);
        const int writeBatch = (out_size >= OUT_BATCH_OFF + NC);
        tail_kernel<<<(NC + 255)/256, 256, 0, s2>>>(out, writePos, writeBatch);
        cudaEventRecord(evTail, s2);
    }

    // main stream: scale 1 (incl. its nbr), then scale 2 (nbr precomputed on s2)
    cudaStreamWaitEvent(0, evCent, 0);
    {
        const int s = 1, K = Kl[1], R = NC * K;
        ushort_t* h1Hi = h1b + hO[s];
        ushort_t* h1Lo = h1Hi + E[s];
        ushort_t* h2Hi = h2b + hO[s];
        ushort_t* h2Lo = h2Hi + E[s];
        int* nbrS = nbrb + nbrOff[s];
        int* cntS = cntb + (size_t)s * NC;

        nbr_kernel<<<NC, 256>>>(pos, r2l[s], K, nbrS, cntS);
        fused_l1<<<R/8, 256>>>(pos, xw + xwOff[s], W[s][0], K, c1[s],
                               nbrS, h1Hi, h1Lo);
        hgemm_pl<128,128,1><<<dim3(R/128,1), 256, smem_pl(128)>>>(
            h1Hi, h1Lo, wpl + w2O[s], wpl + w2O[s] + w2S[s],
            bv[s][1], nullptr, h2Hi, h2Lo, 128);
        hmax_pl<128,128><<<dim3(R/128,2), 256, smem_pl(128)>>>(
            h2Hi, h2Lo, wpl + w3O[s], wpl + w3O[s] + w3S[s],
            bv[s][2], cntS, out, 256, K, coff[s]);
    }
    cudaStreamWaitEvent(0, evNbr2, 0);
    {
        const int s = 2, K = Kl[2], R = NC * K;
        ushort_t* h1Hi = h1b + hO[s];
        ushort_t* h1Lo = h1Hi + E[s];
        ushort_t* h2Hi = h2b + hO[s];
        ushort_t* h2Lo = h2Hi + E[s];
        int* nbrS = nbrb + nbrOff[s];
        int* cntS = cntb + (size_t)s * NC;

        fused_l1<<<R/8, 256>>>(pos, xw + xwOff[s], W[s][0], K, c1[s],
                               nbrS, h1Hi, h1Lo);
        hgemm_pl<128,128,1><<<dim3(R/128,1), 256, smem_pl(128)>>>(
            h1Hi, h1Lo, wpl + w2O[s], wpl + w2O[s] + w2S[s],
            bv[s][1], nullptr, h2Hi, h2Lo, 128);
        hmax_pl<128,128><<<dim3(R/128,2), 256, smem_pl(128)>>>(
            h2Hi, h2Lo, wpl + w3O[s], wpl + w3O[s] + w3S[s],
            bv[s][2], cntS, out, 256, K, coff[s]);
    }

    // final join
    cudaStreamWaitEvent(0, evTail, 0);
}

// round 14
// speedup vs baseline: 1.0006x; 1.0006x over previous
#include <cuda_runtime.h>
#include <cuda_bf16.h>
#include <cstdint>

#define BB  8
#define NN  4096
#define SS  1024
#define CIN 64
#define NC  (BB*SS)          /* 8192 centers */
#define NPTS (BB*NN)         /* 32768 points */

#define OUT_X_ELEMS   (NC*640)
#define OUT_POS_OFF   OUT_X_ELEMS
#define OUT_BATCH_OFF (OUT_X_ELEMS + NC*3)

#define INF_F __int_as_float(0x7f800000)

typedef unsigned short ushort_t;

// ---------------- scratch (__device__ globals: allocation-free contract) ---------
__device__ float    g_centers[NC*3];
__device__ int      g_nbr[NC*112];              // per-scale: K=16,32,64
__device__ int      g_cnt[3*NC];
__device__ float    g_xw[(size_t)NPTS*320];     // x@Wx + b (fp32), all 3 scales
__device__ ushort_t g_h1[218103808];            // h1 planes, all scales (436 MB)
__device__ ushort_t g_h2[218103808];            // h2 planes, all scales (436 MB)
__device__ ushort_t g_xpl[(size_t)2*NPTS*64];   // x planes
__device__ ushort_t g_wpl[1<<19];               // weight planes (transposed)

// ------------------------- helpers ----------------------------------------------
__device__ __forceinline__ void split_bf16(float v, ushort_t& h, ushort_t& l) {
    __nv_bfloat16 hb = __float2bfloat16(v);
    float r = v - __bfloat162float(hb);
    h = __bfloat16_as_ushort(hb);
    l = __bfloat16_as_ushort(__float2bfloat16(r));
}
__device__ __forceinline__ void mma16816(float* c, const uint32_t* a, const uint32_t* b) {
    asm volatile("mma.sync.aligned.m16n8k16.row.col.f32.bf16.bf16.f32 "
                 "{%0,%1,%2,%3}, {%4,%5,%6,%7}, {%8,%9}, {%0,%1,%2,%3};"
                 : "+f"(c[0]), "+f"(c[1]), "+f"(c[2]), "+f"(c[3])
                 : "r"(a[0]), "r"(a[1]), "r"(a[2]), "r"(a[3]),
                   "r"(b[0]), "r"(b[1]));
}
__device__ __forceinline__ uint32_t smem_u32(const void* p) {
    uint32_t a;
    asm("{ .reg .u64 t; cvta.to.shared.u64 t, %1; cvt.u32.u64 %0, t; }" : "=r"(a) : "l"(p));
    return a;
}
__device__ __forceinline__ void cpa16(uint32_t dst, const void* src) {
    asm volatile("cp.async.cg.shared.global [%0], [%1], 16;" :: "r"(dst), "l"(src) : "memory");
}
#define CP_COMMIT() asm volatile("cp.async.commit_group;" ::: "memory")
#define CP_WAIT0()  asm volatile("cp.async.wait_group 0;" ::: "memory")
#define CP_WAIT1()  asm volatile("cp.async.wait_group 1;" ::: "memory")
#define LDSM4(r0,r1,r2,r3,addr) \
    asm volatile("ldmatrix.sync.aligned.m8n8.x4.shared.b16 {%0,%1,%2,%3}, [%4];" \
                 : "=r"(r0), "=r"(r1), "=r"(r2), "=r"(r3) : "r"(addr))

// ============================ conversion kernels =================================
__global__ void xconv(const float* __restrict__ x, ushort_t* __restrict__ hi,
                      ushort_t* __restrict__ lo)
{
    size_t idx = (size_t)blockIdx.x * 256 + threadIdx.x;
    if (idx >= (size_t)NPTS * 64) return;
    ushort_t h, l; split_bf16(x[idx], h, l);
    hi[idx] = h; lo[idx] = l;
}
__global__ void wconv(const float* __restrict__ W, int Nc, int k0, int KC, int N,
                      ushort_t* __restrict__ hi, ushort_t* __restrict__ lo)
{
    int idx = blockIdx.x * 256 + threadIdx.x;
    if (idx >= N * KC) return;
    int n = idx / KC, k = idx % KC;
    ushort_t h, l; split_bf16(W[(size_t)(k0 + k) * Nc + n], h, l);
    hi[idx] = h; lo[idx] = l;
}

// =================================================================================
// Planar bf16 double-split GEMM: cp.async double buffering + ldmatrix frag loads.
// MODE 0: fp32 out, no relu. MODE 1: hi/lo plane out (+relu). rowBase for row-split.
// =================================================================================
template<int KC, int BN, int MODE>
__global__ void __launch_bounds__(256, 2) hgemm_pl(
    const ushort_t* __restrict__ aHi, const ushort_t* __restrict__ aLo,
    const ushort_t* __restrict__ bHi, const ushort_t* __restrict__ bLo,
    const float* __restrict__ bias,
    float* __restrict__ Cf, ushort_t* __restrict__ coHi, ushort_t* __restrict__ coLo,
    int Nc, int rowBase)
{
    extern __shared__ char dsm[];
    constexpr int KP = 40;
    float* s_bias = (float*)(dsm + 2*(128+BN)*KP*2*2);

    const uint32_t base   = smem_u32(dsm);
    const uint32_t AL_OFF = (uint32_t)(2*128*KP*2);
    const uint32_t BH_OFF = AL_OFF * 2;
    const uint32_t BL_OFF = BH_OFF + (uint32_t)(2*BN*KP*2);

    const int tid  = threadIdx.x;
    const int row0 = rowBase + blockIdx.x * 128;
    const int col0 = blockIdx.y * BN;
    if (tid < BN) s_bias[tid] = bias[col0 + tid];

    const int lane = tid & 31, w = tid >> 5;
    const int wm = w & 3, wn = w >> 2;
    constexpr int WN  = BN / 2;
    constexpr int NTL = WN / 8;

    float acc[2][NTL][4];
#pragma unroll
    for (int mt = 0; mt < 2; mt++)
#pragma unroll
        for (int nt = 0; nt < NTL; nt++)
#pragma unroll
            for (int q = 0; q < 4; q++) acc[mt][nt][q] = 0.f;

    constexpr int NKB = KC / 32;

    auto load_stage = [&](int kb, int buf) {
        const int kk = kb * 32;
#pragma unroll
        for (int i = 0; i < 2; i++) {
            int c = tid * 2 + i;
            int row = c >> 2, kc = (c & 3) * 8;
            const ushort_t* s1 = aHi + (size_t)(row0 + row) * KC + kk + kc;
            const ushort_t* s2 = aLo + (size_t)(row0 + row) * KC + kk + kc;
            uint32_t d = base + (uint32_t)((buf * 128 * KP + row * KP + kc) * 2);
            cpa16(d, s1);
            cpa16(d + AL_OFF, s2);
        }
        if (BN == 128) {
#pragma unroll
            for (int i = 0; i < 2; i++) {
                int c = tid * 2 + i;
                int row = c >> 2, kc = (c & 3) * 8;
                const ushort_t* s1 = bHi + (size_t)(col0 + row) * KC + kk + kc;
                const ushort_t* s2 = bLo + (size_t)(col0 + row) * KC + kk + kc;
                uint32_t d = base + BH_OFF + (uint32_t)((buf * BN * KP + row * KP + kc) * 2);
                cpa16(d, s1);
                cpa16(d + (BL_OFF - BH_OFF), s2);
            }
        } else {
            int c = tid;
            int row = c >> 2, kc = (c & 3) * 8;
            const ushort_t* s1 = bHi + (size_t)(col0 + row) * KC + kk + kc;
            const ushort_t* s2 = bLo + (size_t)(col0 + row) * KC + kk + kc;
            uint32_t d = base + BH_OFF + (uint32_t)((buf * BN * KP + row * KP + kc) * 2);
            cpa16(d, s1);
            cpa16(d + (BL_OFF - BH_OFF), s2);
        }
    };

    const int g  = lane >> 3, lr = lane & 7;
    int aoff0[2], boff0[NTL/2];
#pragma unroll
    for (int mt = 0; mt < 2; mt++)
        aoff0[mt] = (wm*32 + mt*16 + (g & 1)*8 + lr) * KP + (g >> 1)*8;
#pragma unroll
    for (int p = 0; p < NTL/2; p++)
        boff0[p] = (wn*WN + p*16 + (g >> 1)*8 + lr) * KP + (g & 1)*8;

    load_stage(0, 0);
    CP_COMMIT();

    int buf = 0;
    for (int kb = 0; kb < NKB; kb++) {
        if (kb + 1 < NKB) { load_stage(kb + 1, buf ^ 1); CP_COMMIT(); CP_WAIT1(); }
        else              { CP_WAIT0(); }
        __syncthreads();

        const uint32_t aBuf = base + (uint32_t)(buf*128*KP*2);
        const uint32_t bBuf = base + BH_OFF + (uint32_t)(buf*BN*KP*2);
#pragma unroll
        for (int k2 = 0; k2 < 32; k2 += 16) {
            uint32_t ah[2][4], al[2][4];
#pragma unroll
            for (int mt = 0; mt < 2; mt++) {
                uint32_t ad = aBuf + (uint32_t)((aoff0[mt] + k2) * 2);
                LDSM4(ah[mt][0], ah[mt][1], ah[mt][2], ah[mt][3], ad);
                LDSM4(al[mt][0], al[mt][1], al[mt][2], al[mt][3], ad + AL_OFF);
            }
            uint32_t bh[NTL][2], bl[NTL][2];
#pragma unroll
            for (int p = 0; p < NTL/2; p++) {
                uint32_t bd = bBuf + (uint32_t)((boff0[p] + k2) * 2);
                LDSM4(bh[2*p][0], bh[2*p][1], bh[2*p+1][0], bh[2*p+1][1], bd);
                LDSM4(bl[2*p][0], bl[2*p][1], bl[2*p+1][0], bl[2*p+1][1],
                      bd + (BL_OFF - BH_OFF));
            }
#pragma unroll
            for (int nt = 0; nt < NTL; nt++)
#pragma unroll
                for (int mt = 0; mt < 2; mt++) {
                    mma16816(acc[mt][nt], ah[mt], bh[nt]);
                    mma16816(acc[mt][nt], ah[mt], bl[nt]);
                    mma16816(acc[mt][nt], al[mt], bh[nt]);
                }
        }
        __syncthreads();
        buf ^= 1;
    }

#pragma unroll
    for (int mt = 0; mt < 2; mt++) {
        int r0 = row0 + wm*32 + mt*16 + (lane>>2);
#pragma unroll
        for (int nt = 0; nt < NTL; nt++) {
            int cc = wn*WN + nt*8 + (lane&3)*2;
            float b0 = s_bias[cc], b1 = s_bias[cc+1];
            float v0 = acc[mt][nt][0] + b0, v1 = acc[mt][nt][1] + b1;
            float v2 = acc[mt][nt][2] + b0, v3 = acc[mt][nt][3] + b1;
            if (MODE == 0) {
                *(float2*)&Cf[(size_t)r0 * Nc + col0 + cc]     = make_float2(v0, v1);
                *(float2*)&Cf[(size_t)(r0+8) * Nc + col0 + cc] = make_float2(v2, v3);
            } else {
                v0 = fmaxf(v0, 0.f); v1 = fmaxf(v1, 0.f);
                v2 = fmaxf(v2, 0.f); v3 = fmaxf(v3, 0.f);
                ushort_t h0,l0,h1,l1;
                split_bf16(v0,h0,l0); split_bf16(v1,h1,l1);
                *(uint32_t*)&coHi[(size_t)r0 * Nc + col0 + cc] = (uint32_t)h0 | ((uint32_t)h1<<16);
                *(uint32_t*)&coLo[(size_t)r0 * Nc + col0 + cc] = (uint32_t)l0 | ((uint32_t)l1<<16);
                split_bf16(v2,h0,l0); split_bf16(v3,h1,l1);
                *(uint32_t*)&coHi[(size_t)(r0+8) * Nc + col0 + cc] = (uint32_t)h0 | ((uint32_t)h1<<16);
                *(uint32_t*)&coLo[(size_t)(r0+8) * Nc + col0 + cc] = (uint32_t)l0 | ((uint32_t)l1<<16);
            }
        }
    }
}

// =================================================================================
// Planar GEMM + bias + relu + masked segment-max epilogue (last layer). rowBase
// for row-split across streams (rowBase % 128 == 0, K | 128 keeps centers intact).
// =================================================================================
template<int KC, int BN>
__global__ void __launch_bounds__(256, 2) hmax_pl(
    const ushort_t* __restrict__ aHi, const ushort_t* __restrict__ aLo,
    const ushort_t* __restrict__ bHi, const ushort_t* __restrict__ bLo,
    const float* __restrict__ bias, const int* __restrict__ cnt,
    float* __restrict__ out, int Nc, int Kn, int colOff, int rowBase)
{
    extern __shared__ char dsm[];
    constexpr int KP = 40;
    float* s_bias = (float*)(dsm + 2*(128+BN)*KP*2*2);
    float* red    = (float*)dsm;

    const uint32_t base   = smem_u32(dsm);
    const uint32_t AL_OFF = (uint32_t)(2*128*KP*2);
    const uint32_t BH_OFF = AL_OFF * 2;
    const uint32_t BL_OFF = BH_OFF + (uint32_t)(2*BN*KP*2);

    const int tid  = threadIdx.x;
    const int row0 = rowBase + blockIdx.x * 128;
    const int col0 = blockIdx.y * BN;
    if (tid < BN) s_bias[tid] = bias[col0 + tid];

    const int lane = tid & 31, w = tid >> 5;
    const int wm = w & 3, wn = w >> 2;
    constexpr int WN  = BN / 2;
    constexpr int NTL = WN / 8;

    float acc[2][NTL][4];
#pragma unroll
    for (int mt = 0; mt < 2; mt++)
#pragma unroll
        for (int nt = 0; nt < NTL; nt++)
#pragma unroll
            for (int q = 0; q < 4; q++) acc[mt][nt][q] = 0.f;

    constexpr int NKB = KC / 32;

    auto load_stage = [&](int kb, int buf) {
        const int kk = kb * 32;
#pragma unroll
        for (int i = 0; i < 2; i++) {
            int c = tid * 2 + i;
            int row = c >> 2, kc = (c & 3) * 8;
            const ushort_t* s1 = aHi + (size_t)(row0 + row) * KC + kk + kc;
            const ushort_t* s2 = aLo + (size_t)(row0 + row) * KC + kk + kc;
            uint32_t d = base + (uint32_t)((buf * 128 * KP + row * KP + kc) * 2);
            cpa16(d, s1);
            cpa16(d + AL_OFF, s2);
        }
#pragma unroll
        for (int i = 0; i < 2; i++) {
            int c = tid * 2 + i;
            int row = c >> 2, kc = (c & 3) * 8;
            const ushort_t* s1 = bHi + (size_t)(col0 + row) * KC + kk + kc;
            const ushort_t* s2 = bLo + (size_t)(col0 + row) * KC + kk + kc;
            uint32_t d = base + BH_OFF + (uint32_t)((buf * BN * KP + row * KP + kc) * 2);
            cpa16(d, s1);
            cpa16(d + (BL_OFF - BH_OFF), s2);
        }
    };

    const int g  = lane >> 3, lr = lane & 7;
    int aoff0[2], boff0[NTL/2];
#pragma unroll
    for (int mt = 0; mt < 2; mt++)
        aoff0[mt] = (wm*32 + mt*16 + (g & 1)*8 + lr) * KP + (g >> 1)*8;
#pragma unroll
    for (int p = 0; p < NTL/2; p++)
        boff0[p] = (wn*WN + p*16 + (g >> 1)*8 + lr) * KP + (g & 1)*8;

    load_stage(0, 0);
    CP_COMMIT();

    int buf = 0;
    for (int kb = 0; kb < NKB; kb++) {
        if (kb + 1 < NKB) { load_stage(kb + 1, buf ^ 1); CP_COMMIT(); CP_WAIT1(); }
        else              { CP_WAIT0(); }
        __syncthreads();

        const uint32_t aBuf = base + (uint32_t)(buf*128*KP*2);
        const uint32_t bBuf = base + BH_OFF + (uint32_t)(buf*BN*KP*2);
#pragma unroll
        for (int k2 = 0; k2 < 32; k2 += 16) {
            uint32_t ah[2][4], al[2][4];
#pragma unroll
            for (int mt = 0; mt < 2; mt++) {
                uint32_t ad = aBuf + (uint32_t)((aoff0[mt] + k2) * 2);
                LDSM4(ah[mt][0], ah[mt][1], ah[mt][2], ah[mt][3], ad);
                LDSM4(al[mt][0], al[mt][1], al[mt][2], al[mt][3], ad + AL_OFF);
            }
            uint32_t bh[NTL][2], bl[NTL][2];
#pragma unroll
            for (int p = 0; p < NTL/2; p++) {
                uint32_t bd = bBuf + (uint32_t)((boff0[p] + k2) * 2);
                LDSM4(bh[2*p][0], bh[2*p][1], bh[2*p+1][0], bh[2*p+1][1], bd);
                LDSM4(bl[2*p][0], bl[2*p][1], bl[2*p+1][0], bl[2*p+1][1],
                      bd + (BL_OFF - BH_OFF));
            }
#pragma unroll
            for (int nt = 0; nt < NTL; nt++)
#pragma unroll
                for (int mt = 0; mt < 2; mt++) {
                    mma16816(acc[mt][nt], ah[mt], bh[nt]);
                    mma16816(acc[mt][nt], ah[mt], bl[nt]);
                    mma16816(acc[mt][nt], al[mt], bh[nt]);
                }
        }
        __syncthreads();
        buf ^= 1;
    }

#pragma unroll
    for (int mt = 0; mt < 2; mt++) {
        int lr2 = wm*32 + mt*16 + (lane>>2);
        int ok0 = (lr2 % Kn)     < cnt[(row0 + lr2) / Kn];
        int ok1 = ((lr2+8) % Kn) < cnt[(row0 + lr2 + 8) / Kn];
#pragma unroll
        for (int nt = 0; nt < NTL; nt++) {
            int cc = wn*WN + nt*8 + (lane&3)*2;
            float b0 = s_bias[cc], b1 = s_bias[cc+1];
            float v0 = fmaxf(acc[mt][nt][0] + b0, 0.f);
            float v1 = fmaxf(acc[mt][nt][1] + b1, 0.f);
            float v2 = fmaxf(acc[mt][nt][2] + b0, 0.f);
            float v3 = fmaxf(acc[mt][nt][3] + b1, 0.f);
            red[(size_t)lr2*(BN+1) + cc]         = ok0 ? v0 : -INF_F;
            red[(size_t)lr2*(BN+1) + cc + 1]     = ok0 ? v1 : -INF_F;
            red[(size_t)(lr2+8)*(BN+1) + cc]     = ok1 ? v2 : -INF_F;
            red[(size_t)(lr2+8)*(BN+1) + cc + 1] = ok1 ? v3 : -INF_F;
        }
    }
    __syncthreads();

    const int nseg = 128 / Kn;
    const int cb   = row0 / Kn;
    for (int o = tid; o < nseg * BN; o += 256) {
        int seg = o / BN, col = o % BN;
        float m = -INF_F;
        int rb = seg * Kn;
        for (int r = 0; r < Kn; r++)
            m = fmaxf(m, red[(size_t)(rb + r)*(BN+1) + col]);
        out[(size_t)(cb + seg) * 640 + colOff + col0 + col] = m;
    }
}

// =================================================================================
// 1) Farthest point sampling — single barrier/step (bitwise-frozen math)
// =================================================================================
__global__ void __launch_bounds__(1024) fps_kernel(const float* __restrict__ pos)
{
    const int b    = blockIdx.x;
    const int tid  = threadIdx.x;
    const int lane = tid & 31, wid = tid >> 5;
    const float* p = pos + (size_t)b * NN * 3;

    __shared__ float s_xyz[NN*3];
    __shared__ float s_v[2][32];
    __shared__ int   s_i[2][32];

    for (int i = tid; i < NN*3; i += 1024) s_xyz[i] = p[i];

    float px[4], py[4], pz[4], md[4];
#pragma unroll
    for (int i = 0; i < 4; i++) {
        int j = tid * 4 + i;
        px[i] = p[j*3+0]; py[i] = p[j*3+1]; pz[i] = p[j*3+2];
        md[i] = INF_F;
    }

    float cx = p[0], cy = p[1], cz = p[2];
    if (tid == 0) {
        size_t o = (size_t)b * SS * 3;
        g_centers[o] = cx; g_centers[o+1] = cy; g_centers[o+2] = cz;
    }
    __syncthreads();

    int par = 0;
    for (int s = 1; s < SS; s++) {
        float bv = -1.0f; int bi = 0;
#pragma unroll
        for (int i = 0; i < 4; i++) {
            float dx = __fsub_rn(px[i], cx);
            float dy = __fsub_rn(py[i], cy);
            float dz = __fsub_rn(pz[i], cz);
            float d2 = __fadd_rn(__fadd_rn(__fmul_rn(dx,dx), __fmul_rn(dy,dy)),
                                 __fmul_rn(dz,dz));
            md[i] = fminf(md[i], d2);
            if (md[i] > bv) { bv = md[i]; bi = tid*4 + i; }
        }
        unsigned ubv  = __float_as_uint(bv);
        unsigned wmax = __reduce_max_sync(0xffffffffu, ubv);
        unsigned ball = __ballot_sync(0xffffffffu, ubv == wmax);
        int src = __ffs(ball) - 1;
        int wbi = __shfl_sync(0xffffffffu, bi, src);
        if (lane == 0) { s_v[par][wid] = __uint_as_float(wmax); s_i[par][wid] = wbi; }
        __syncthreads();

        unsigned v  = __float_as_uint(s_v[par][lane]);
        int      iv = s_i[par][lane];
        unsigned m2 = __reduce_max_sync(0xffffffffu, v);
        unsigned ba = __ballot_sync(0xffffffffu, v == m2);
        int sc = __ffs(ba) - 1;
        int i2 = __shfl_sync(0xffffffffu, iv, sc);

        cx = s_xyz[i2*3+0]; cy = s_xyz[i2*3+1]; cz = s_xyz[i2*3+2];
        if (tid == 0) {
            size_t o = ((size_t)b*SS + s) * 3;
            g_centers[o] = cx; g_centers[o+1] = cy; g_centers[o+2] = cz;
        }
        par ^= 1;
    }
}

// =================================================================================
// 2) Radius ball query + exact top-K (per-scale output pointers)
// =================================================================================
__global__ void __launch_bounds__(256) nbr_kernel(const float* __restrict__ pos,
                                                  float r2, int Kn,
                                                  int* __restrict__ nbrOut,
                                                  int* __restrict__ cntOut)
{
    __shared__ unsigned long long keys[4096];
    __shared__ int s_count;
    const int ci  = blockIdx.x;
    const int b   = ci / SS;
    const int tid = threadIdx.x;
    if (tid == 0) s_count = 0;
    __syncthreads();

    const float cx = g_centers[ci*3+0], cy = g_centers[ci*3+1], cz = g_centers[ci*3+2];
    const float* p = pos + (size_t)b * NN * 3;

    for (int j = tid; j < NN; j += 256) {
        float dx = __fsub_rn(cx, p[j*3+0]);
        float dy = __fsub_rn(cy, p[j*3+1]);
        float dz = __fsub_rn(cz, p[j*3+2]);
        float d2 = __fadd_rn(__fadd_rn(__fmul_rn(dx,dx), __fmul_rn(dy,dy)),
                             __fmul_rn(dz,dz));
        if (d2 <= r2) {
            int w = atomicAdd(&s_count, 1);
            keys[w] = (((unsigned long long)__float_as_uint(d2)) << 32) | (unsigned)j;
        }
    }
    __syncthreads();
    const int M = s_count;
    int n = 16;
    while (n < M || n < Kn) n <<= 1;
    for (int i = M + tid; i < n; i += 256) keys[i] = 0xFFFFFFFFFFFFFFFFULL;
    __syncthreads();

    for (int size = 2; size <= n; size <<= 1) {
        for (int stride = size >> 1; stride > 0; stride >>= 1) {
            for (int i = tid; i < (n >> 1); i += 256) {
                int p0 = 2*i - (i & (stride - 1));
                int p1 = p0 + stride;
                unsigned long long a = keys[p0], c = keys[p1];
                bool asc = ((p0 & size) == 0);
                if (asc ? (a > c) : (a < c)) { keys[p0] = c; keys[p1] = a; }
            }
            __syncthreads();
        }
    }

    for (int k = tid; k < Kn; k += 256) {
        int j = (k < M) ? (int)(keys[k] & 0xFFFFFFFFu) : 0;
        nbrOut[(size_t)ci * Kn + k] = b * NN + j;
    }
    if (tid == 0) cntOut[ci] = (M < Kn) ? M : Kn;
}

// =================================================================================
// 3) Fused gather + layer-1 (emits h1 bf16 hi/lo planes; per-scale nbr pointer)
// =================================================================================
__global__ void __launch_bounds__(256) fused_l1(const float* __restrict__ pos,
                                                const float* __restrict__ xwb,
                                                const float* __restrict__ W1,
                                                int Kn, int c1,
                                                const int* __restrict__ nbr,
                                                ushort_t* __restrict__ hHi,
                                                ushort_t* __restrict__ hLo)
{
    __shared__ float s_wp[3*128];
    const int tid  = threadIdx.x;
    for (int i = tid; i < 3 * c1; i += 256)
        s_wp[i] = W1[(size_t)(64 + i / c1) * c1 + (i % c1)];
    __syncthreads();

    const int warp = tid >> 5, lane = tid & 31;
    const long row = (long)blockIdx.x * 8 + warp;
    const int  ci  = (int)(row / Kn);
    const int  j   = nbr[row];

    const float p0 = __fsub_rn(pos[(size_t)j*3+0], g_centers[(size_t)ci*3+0]);
    const float p1 = __fsub_rn(pos[(size_t)j*3+1], g_centers[(size_t)ci*3+1]);
    const float p2 = __fsub_rn(pos[(size_t)j*3+2], g_centers[(size_t)ci*3+2]);

    const float* xr = xwb + (size_t)j * c1;
    const size_t rb = (size_t)row * c1;
#pragma unroll 2
    for (int it = 0; it < c1/64; it++) {
        int cc = lane*2 + it*64;
        float v0 = xr[cc], v1 = xr[cc+1];
        v0 = fmaf(p0, s_wp[cc],          v0);
        v0 = fmaf(p1, s_wp[c1 + cc],     v0);
        v0 = fmaf(p2, s_wp[2*c1 + cc],   v0);
        v1 = fmaf(p0, s_wp[cc+1],        v1);
        v1 = fmaf(p1, s_wp[c1 + cc+1],   v1);
        v1 = fmaf(p2, s_wp[2*c1 + cc+1], v1);
        v0 = fmaxf(v0, 0.f); v1 = fmaxf(v1, 0.f);
        ushort_t h0,l0,h1,l1;
        split_bf16(v0,h0,l0); split_bf16(v1,h1,l1);
        *(uint32_t*)&hHi[rb + cc] = (uint32_t)h0 | ((uint32_t)h1<<16);
        *(uint32_t*)&hLo[rb + cc] = (uint32_t)l0 | ((uint32_t)l1<<16);
    }
}

// =================================================================================
// 4) new_pos / new_batch tail
// =================================================================================
__global__ void tail_kernel(float* __restrict__ out, int writePos, int writeBatch)
{
    int i = blockIdx.x * blockDim.x + threadIdx.x;
    if (i >= NC) return;
    if (writePos) {
        out[OUT_POS_OFF + i*3 + 0] = g_centers[i*3+0];
        out[OUT_POS_OFF + i*3 + 1] = g_centers[i*3+1];
        out[OUT_POS_OFF + i*3 + 2] = g_centers[i*3+2];
    }
    if (writeBatch) out[OUT_BATCH_OFF + i] = (float)(i / SS);
}

// =================================================================================
static inline int smem_pl(int BN) { return 320 * (128 + BN) + 512; }

extern "C" void kernel_launch(void* const* d_in, const int* in_sizes, int n_in,
                              void* d_out, int out_size)
{
    const float* x   = (const float*)d_in[0];
    const float* pos = (const float*)d_in[1];
    const float* W[3][3];
    const float* bv[3][3];
    int ii = 3;
    for (int s = 0; s < 3; s++)
        for (int l = 0; l < 3; l++) {
            W[s][l]  = (const float*)d_in[ii++];
            bv[s][l] = (const float*)d_in[ii++];
        }
    float* out = (float*)d_out;

    void *pX = nullptr, *pXP = nullptr, *pWP = nullptr, *pH1 = nullptr, *pH2 = nullptr;
    void *pNB = nullptr, *pCT = nullptr;
    cudaGetSymbolAddress(&pX, g_xw);
    cudaGetSymbolAddress(&pXP, g_xpl);
    cudaGetSymbolAddress(&pWP, g_wpl);
    cudaGetSymbolAddress(&pH1, g_h1);
    cudaGetSymbolAddress(&pH2, g_h2);
    cudaGetSymbolAddress(&pNB, g_nbr);
    cudaGetSymbolAddress(&pCT, g_cnt);
    float*    xw   = (float*)pX;
    ushort_t* xpl  = (ushort_t*)pXP;
    ushort_t* wpl  = (ushort_t*)pWP;
    ushort_t* h1b  = (ushort_t*)pH1;
    ushort_t* h2b  = (ushort_t*)pH2;
    int*      nbrb = (int*)pNB;
    int*      cntb = (int*)pCT;

    cudaFuncSetAttribute(hgemm_pl<64,64,0>,   cudaFuncAttributeMaxDynamicSharedMemorySize, smem_pl(64));
    cudaFuncSetAttribute(hgemm_pl<64,128,0>,  cudaFuncAttributeMaxDynamicSharedMemorySize, smem_pl(128));
    cudaFuncSetAttribute(hgemm_pl<64,64,1>,   cudaFuncAttributeMaxDynamicSharedMemorySize, smem_pl(64));
    cudaFuncSetAttribute(hgemm_pl<128,128,1>, cudaFuncAttributeMaxDynamicSharedMemorySize, smem_pl(128));
    cudaFuncSetAttribute(hmax_pl<64,128>,     cudaFuncAttributeMaxDynamicSharedMemorySize, smem_pl(128));
    cudaFuncSetAttribute(hmax_pl<128,128>,    cudaFuncAttributeMaxDynamicSharedMemorySize, smem_pl(128));

    const int    Kl[3]    = {16, 32, 64};
    const float  r2l[3]   = {(float)(0.1*0.1), (float)(0.2*0.2), (float)(0.4*0.4)};
    const int    c1[3]    = {64, 128, 128};
    const int    coff[3]  = {0, 128, 384};
    const size_t xwOff[3] = {0, (size_t)NPTS*64, (size_t)NPTS*(64+128)};
    const size_t E[3]  = {(size_t)NC*16*64, (size_t)NC*32*128, (size_t)NC*64*128};
    const size_t hO[3] = {0, 2*E[0], 2*E[0] + 2*E[1]};
    const size_t nbrOff[3] = {0, (size_t)NC*16, (size_t)NC*(16+32)};

    size_t woff = 0;
    size_t wxO[3], w2O[3], w3O[3], wxS[3], w2S[3], w3S[3];
    for (int s = 0; s < 3; s++) {
        wxS[s] = (size_t)64 * c1[s];    wxO[s] = woff; woff += 2*wxS[s];
        w2S[s] = (size_t)c1[s] * (s ? 128 : 64); w2O[s] = woff; woff += 2*w2S[s];
        w3S[s] = (size_t)(s ? 128 : 64) * (s ? 256 : 128); w3O[s] = woff; woff += 2*w3S[s];
    }

    // ---- 2-stream envelope (proven in R9/R12/R13) -------------------------------
    cudaStream_t s2;
    cudaStreamCreateWithFlags(&s2, cudaStreamNonBlocking);
    cudaEvent_t evFork, evCent, evXw0, evXw2, evL12, evTail;
    cudaEventCreateWithFlags(&evFork, cudaEventDisableTiming);
    cudaEventCreateWithFlags(&evCent, cudaEventDisableTiming);
    cudaEventCreateWithFlags(&evXw0,  cudaEventDisableTiming);
    cudaEventCreateWithFlags(&evXw2,  cudaEventDisableTiming);
    cudaEventCreateWithFlags(&evL12,  cudaEventDisableTiming);
    cudaEventCreateWithFlags(&evTail, cudaEventDisableTiming);

    cudaEventRecord(evFork, 0);
    cudaStreamWaitEvent(s2, evFork, 0);

    // side stream: fps
    fps_kernel<<<BB, 1024, 0, s2>>>(pos);
    cudaEventRecord(evCent, s2);

    // main stream: conversions + xw GEMMs
    xconv<<<(int)(((size_t)NPTS*64 + 255)/256), 256>>>(x, xpl, xpl + (size_t)NPTS*64);
    for (int s = 0; s < 3; s++) {
        const int c2v = s ? 128 : 64, c3v = s ? 256 : 128;
        wconv<<<(int)((wxS[s]+255)/256), 256>>>(W[s][0], c1[s], 0, 64, c1[s],
                                                wpl + wxO[s], wpl + wxO[s] + wxS[s]);
        wconv<<<(int)((w2S[s]+255)/256), 256>>>(W[s][1], c2v, 0, c1[s], c2v,
                                                wpl + w2O[s], wpl + w2O[s] + w2S[s]);
        wconv<<<(int)((w3S[s]+255)/256), 256>>>(W[s][2], c3v, 0, c2v, c3v,
                                                wpl + w3O[s], wpl + w3O[s] + w3S[s]);
    }
    hgemm_pl<64,64,0><<<dim3(NPTS/128,1), 256, smem_pl(64)>>>(
        xpl, xpl + (size_t)NPTS*64, wpl + wxO[0], wpl + wxO[0] + wxS[0],
        bv[0][0], xw + xwOff[0], nullptr, nullptr, 64, 0);
    cudaEventRecord(evXw0, 0);
    hgemm_pl<64,128,0><<<dim3(NPTS/128,1), 256, smem_pl(128)>>>(
        xpl, xpl + (size_t)NPTS*64, wpl + wxO[1], wpl + wxO[1] + wxS[1],
        bv[1][0], xw + xwOff[1], nullptr, nullptr, 128, 0);
    hgemm_pl<64,128,0><<<dim3(NPTS/128,1), 256, smem_pl(128)>>>(
        xpl, xpl + (size_t)NPTS*64, wpl + wxO[2], wpl + wxO[2] + wxS[2],
        bv[2][0], xw + xwOff[2], nullptr, nullptr, 128, 0);
    cudaEventRecord(evXw2, 0);

    // --- pointer sets ---
    ushort_t* h1Hi0 = h1b + hO[0]; ushort_t* h1Lo0 = h1Hi0 + E[0];
    ushort_t* h2Hi0 = h2b + hO[0]; ushort_t* h2Lo0 = h2Hi0 + E[0];
    ushort_t* h1Hi1 = h1b + hO[1]; ushort_t* h1Lo1 = h1Hi1 + E[1];
    ushort_t* h2Hi1 = h2b + hO[1]; ushort_t* h2Lo1 = h2Hi1 + E[1];
    ushort_t* h1Hi2 = h1b + hO[2]; ushort_t* h1Lo2 = h1Hi2 + E[2];
    ushort_t* h2Hi2 = h2b + hO[2]; ushort_t* h2Lo2 = h2Hi2 + E[2];
    const int R2 = NC * Kl[2];           // 524288
    const int R2H = R2 / 2;              // row split point (multiple of 128 & K)

    // side stream: nbr0, nbr2, s0 chain, l1_2, s2 lo-half chain, tail
    {
        const int K = Kl[0], R = NC * K;
        nbr_kernel<<<NC, 256, 0, s2>>>(pos, r2l[0], K, nbrb + nbrOff[0], cntb);
        nbr_kernel<<<NC, 256, 0, s2>>>(pos, r2l[2], Kl[2],
                                       nbrb + nbrOff[2], cntb + 2*NC);

        cudaStreamWaitEvent(s2, evXw0, 0);
        fused_l1<<<R/8, 256, 0, s2>>>(pos, xw + xwOff[0], W[0][0], K, c1[0],
                                      nbrb + nbrOff[0], h1Hi0, h1Lo0);
        hgemm_pl<64,64,1><<<dim3(R/128,1), 256, smem_pl(64), s2>>>(
            h1Hi0, h1Lo0, wpl + w2O[0], wpl + w2O[0] + w2S[0],
            bv[0][1], nullptr, h2Hi0, h2Lo0, 64, 0);
        hmax_pl<64,128><<<dim3(R/128,1), 256, smem_pl(128), s2>>>(
            h2Hi0, h2Lo0, wpl + w3O[0], wpl + w3O[0] + w3S[0],
            bv[0][2], cntb, out, 128, K, coff[0], 0);

        cudaStreamWaitEvent(s2, evXw2, 0);
        fused_l1<<<R2/8, 256, 0, s2>>>(pos, xw + xwOff[2], W[2][0], Kl[2], c1[2],
                                       nbrb + nbrOff[2], h1Hi2, h1Lo2);
        cudaEventRecord(evL12, s2);

        // s2 lo-half
        hgemm_pl<128,128,1><<<dim3(R2H/128,1), 256, smem_pl(128), s2>>>(
            h1Hi2, h1Lo2, wpl + w2O[2], wpl + w2O[2] + w2S[2],
            bv[2][1], nullptr, h2Hi2, h2Lo2, 128, 0);
        hmax_pl<128,128><<<dim3(R2H/128,2), 256, smem_pl(128), s2>>>(
            h2Hi2, h2Lo2, wpl + w3O[2], wpl + w3O[2] + w3S[2],
            bv[2][2], cntb + 2*NC, out, 256, Kl[2], coff[2], 0);

        const int writePos   = (out_size >= OUT_POS_OFF + NC*3);
        const int writeBatch = (out_size >= OUT_BATCH_OFF + NC);
        tail_kernel<<<(NC + 255)/256, 256, 0, s2>>>(out, writePos, writeBatch);
        cudaEventRecord(evTail, s2);
    }

    // main stream: scale 1 full chain, then s2 hi-half
    cudaStreamWaitEvent(0, evCent, 0);
    {
        const int s = 1, K = Kl[1], R = NC * K;
        nbr_kernel<<<NC, 256>>>(pos, r2l[s], K, nbrb + nbrOff[s], cntb + NC);
        fused_l1<<<R/8, 256>>>(pos, xw + xwOff[s], W[s][0], K, c1[s],
                               nbrb + nbrOff[s], h1Hi1, h1Lo1);
        hgemm_pl<128,128,1><<<dim3(R/128,1), 256, smem_pl(128)>>>(
            h1Hi1, h1Lo1, wpl + w2O[s], wpl + w2O[s] + w2S[s],
            bv[s][1], nullptr, h2Hi1, h2Lo1, 128, 0);
        hmax_pl<128,128><<<dim3(R/128,2), 256, smem_pl(128)>>>(
            h2Hi1, h2Lo1, wpl + w3O[s], wpl + w3O[s] + w3S[s],
            bv[s][2], cntb + NC, out, 256, K, coff[s], 0);
    }
    cudaStreamWaitEvent(0, evL12, 0);
    {
        // s2 hi-half
        hgemm_pl<128,128,1><<<dim3(R2H/128,1), 256, smem_pl(128)>>>(
            h1Hi2, h1Lo2, wpl + w2O[2], wpl + w2O[2] + w2S[2],
            bv[2][1], nullptr, h2Hi2, h2Lo2, 128, R2H);
        hmax_pl<128,128><<<dim3(R2H/128,2), 256, smem_pl(128)>>>(
            h2Hi2, h2Lo2, wpl + w3O[2], wpl + w3O[2] + w3S[2],
            bv[2][2], cntb + 2*NC, out, 256, Kl[2], coff[2], R2H);
    }

    // final join
    cudaStreamWaitEvent(0, evTail, 0);
}

// round 16
// speedup vs baseline: 1.1575x; 1.1569x over previous
#include <cuda_runtime.h>
#include <cuda_fp16.h>
#include <cstdint>

#define BB  8
#define NN  4096
#define SS  1024
#define CIN 64
#define NC  (BB*SS)          /* 8192 centers */
#define NPTS (BB*NN)         /* 32768 points */

#define OUT_X_ELEMS   (NC*640)
#define OUT_POS_OFF   OUT_X_ELEMS
#define OUT_BATCH_OFF (OUT_X_ELEMS + NC*3)

#define INF_F __int_as_float(0x7f800000)

typedef unsigned short ushort_t;

// ---------------- scratch (__device__ globals: allocation-free contract) ---------
__device__ float    g_centers[NC*3];
__device__ int      g_nbr[NC*112];              // per-scale: K=16,32,64
__device__ int      g_cnt[3*NC];
__device__ float    g_xw[(size_t)NPTS*320];     // x@Wx + b (fp32), all 3 scales
__device__ ushort_t g_h1[109051904];            // h1 fp16 planes (single), all scales
__device__ ushort_t g_h2[109051904];            // h2 fp16 planes (single), all scales
__device__ ushort_t g_xpl[(size_t)NPTS*64];     // x fp16 plane (single)
__device__ ushort_t g_wpl[1<<19];               // weight fp16 planes (hi+lo, transposed)

// ------------------------- helpers ----------------------------------------------
__device__ __forceinline__ ushort_t to_fp16(float v) {
    return __half_as_ushort(__float2half_rn(v));
}
__device__ __forceinline__ void split_fp16(float v, ushort_t& h, ushort_t& l) {
    __half hb = __float2half_rn(v);
    float r = v - __half2float(hb);
    h = __half_as_ushort(hb);
    l = __half_as_ushort(__float2half_rn(r));
}
__device__ __forceinline__ void mma16816f(float* c, const uint32_t* a, const uint32_t* b) {
    asm volatile("mma.sync.aligned.m16n8k16.row.col.f32.f16.f16.f32 "
                 "{%0,%1,%2,%3}, {%4,%5,%6,%7}, {%8,%9}, {%0,%1,%2,%3};"
                 : "+f"(c[0]), "+f"(c[1]), "+f"(c[2]), "+f"(c[3])
                 : "r"(a[0]), "r"(a[1]), "r"(a[2]), "r"(a[3]),
                   "r"(b[0]), "r"(b[1]));
}
__device__ __forceinline__ uint32_t smem_u32(const void* p) {
    uint32_t a;
    asm("{ .reg .u64 t; cvta.to.shared.u64 t, %1; cvt.u32.u64 %0, t; }" : "=r"(a) : "l"(p));
    return a;
}
__device__ __forceinline__ void cpa16(uint32_t dst, const void* src) {
    asm volatile("cp.async.cg.shared.global [%0], [%1], 16;" :: "r"(dst), "l"(src) : "memory");
}
#define CP_COMMIT() asm volatile("cp.async.commit_group;" ::: "memory")
#define CP_WAIT0()  asm volatile("cp.async.wait_group 0;" ::: "memory")
#define CP_WAIT1()  asm volatile("cp.async.wait_group 1;" ::: "memory")
#define LDSM4(r0,r1,r2,r3,addr) \
    asm volatile("ldmatrix.sync.aligned.m8n8.x4.shared.b16 {%0,%1,%2,%3}, [%4];" \
                 : "=r"(r0), "=r"(r1), "=r"(r2), "=r"(r3) : "r"(addr))

// ============================ conversion kernels =================================
__global__ void xconv(const float* __restrict__ x, ushort_t* __restrict__ hp)
{
    size_t idx = (size_t)blockIdx.x * 256 + threadIdx.x;
    if (idx >= (size_t)NPTS * 64) return;
    hp[idx] = to_fp16(x[idx]);
}
__global__ void wconv(const float* __restrict__ W, int Nc, int k0, int KC, int N,
                      ushort_t* __restrict__ hi, ushort_t* __restrict__ lo)
{
    int idx = blockIdx.x * 256 + threadIdx.x;
    if (idx >= N * KC) return;
    int n = idx / KC, k = idx % KC;
    ushort_t h, l; split_fp16(W[(size_t)(k0 + k) * Nc + n], h, l);
    hi[idx] = h; lo[idx] = l;
}

// =================================================================================
// fp16 GEMM, A single plane, B hi/lo double-split (2 MMAs per logical k16).
// cp.async double buffering + ldmatrix. MODE 0: fp32 out. MODE 1: fp16 plane (+relu).
// =================================================================================
template<int KC, int BN, int MODE>
__global__ void __launch_bounds__(256, 2) hgemm_pl(
    const ushort_t* __restrict__ aH,
    const ushort_t* __restrict__ bHi, const ushort_t* __restrict__ bLo,
    const float* __restrict__ bias,
    float* __restrict__ Cf, ushort_t* __restrict__ coH,
    int Nc, int rowBase)
{
    extern __shared__ char dsm[];
    constexpr int KP = 40;
    const uint32_t BH_OFF = (uint32_t)(2*128*KP*2);
    const uint32_t BL_OFF = BH_OFF + (uint32_t)(2*BN*KP*2);
    float* s_bias = (float*)(dsm + BL_OFF + 2*BN*KP*2);

    const uint32_t base = smem_u32(dsm);

    const int tid  = threadIdx.x;
    const int row0 = rowBase + blockIdx.x * 128;
    const int col0 = blockIdx.y * BN;
    if (tid < BN) s_bias[tid] = bias[col0 + tid];

    const int lane = tid & 31, w = tid >> 5;
    const int wm = w & 3, wn = w >> 2;
    constexpr int WN  = BN / 2;
    constexpr int NTL = WN / 8;

    float acc[2][NTL][4];
#pragma unroll
    for (int mt = 0; mt < 2; mt++)
#pragma unroll
        for (int nt = 0; nt < NTL; nt++)
#pragma unroll
            for (int q = 0; q < 4; q++) acc[mt][nt][q] = 0.f;

    constexpr int NKB = KC / 32;

    auto load_stage = [&](int kb, int buf) {
        const int kk = kb * 32;
#pragma unroll
        for (int i = 0; i < 2; i++) {
            int c = tid * 2 + i;
            int row = c >> 2, kc = (c & 3) * 8;
            cpa16(base + (uint32_t)((buf * 128 * KP + row * KP + kc) * 2),
                  aH + (size_t)(row0 + row) * KC + kk + kc);
        }
        if (BN == 128) {
#pragma unroll
            for (int i = 0; i < 2; i++) {
                int c = tid * 2 + i;
                int row = c >> 2, kc = (c & 3) * 8;
                uint32_t d = base + BH_OFF + (uint32_t)((buf * BN * KP + row * KP + kc) * 2);
                cpa16(d,                     bHi + (size_t)(col0 + row) * KC + kk + kc);
                cpa16(d + (BL_OFF - BH_OFF), bLo + (size_t)(col0 + row) * KC + kk + kc);
            }
        } else {
            int c = tid;
            int row = c >> 2, kc = (c & 3) * 8;
            uint32_t d = base + BH_OFF + (uint32_t)((buf * BN * KP + row * KP + kc) * 2);
            cpa16(d,                     bHi + (size_t)(col0 + row) * KC + kk + kc);
            cpa16(d + (BL_OFF - BH_OFF), bLo + (size_t)(col0 + row) * KC + kk + kc);
        }
    };

    const int g  = lane >> 3, lr = lane & 7;
    int aoff0[2], boff0[NTL/2];
#pragma unroll
    for (int mt = 0; mt < 2; mt++)
        aoff0[mt] = (wm*32 + mt*16 + (g & 1)*8 + lr) * KP + (g >> 1)*8;
#pragma unroll
    for (int p = 0; p < NTL/2; p++)
        boff0[p] = (wn*WN + p*16 + (g >> 1)*8 + lr) * KP + (g & 1)*8;

    load_stage(0, 0);
    CP_COMMIT();

    int buf = 0;
    for (int kb = 0; kb < NKB; kb++) {
        if (kb + 1 < NKB) { load_stage(kb + 1, buf ^ 1); CP_COMMIT(); CP_WAIT1(); }
        else              { CP_WAIT0(); }
        __syncthreads();

        const uint32_t aBuf = base + (uint32_t)(buf*128*KP*2);
        const uint32_t bBuf = base + BH_OFF + (uint32_t)(buf*BN*KP*2);
#pragma unroll
        for (int k2 = 0; k2 < 32; k2 += 16) {
            uint32_t ah[2][4];
#pragma unroll
            for (int mt = 0; mt < 2; mt++) {
                uint32_t ad = aBuf + (uint32_t)((aoff0[mt] + k2) * 2);
                LDSM4(ah[mt][0], ah[mt][1], ah[mt][2], ah[mt][3], ad);
            }
            uint32_t bh[NTL][2], bl[NTL][2];
#pragma unroll
            for (int p = 0; p < NTL/2; p++) {
                uint32_t bd = bBuf + (uint32_t)((boff0[p] + k2) * 2);
                LDSM4(bh[2*p][0], bh[2*p][1], bh[2*p+1][0], bh[2*p+1][1], bd);
                LDSM4(bl[2*p][0], bl[2*p][1], bl[2*p+1][0], bl[2*p+1][1],
                      bd + (BL_OFF - BH_OFF));
            }
#pragma unroll
            for (int nt = 0; nt < NTL; nt++)
#pragma unroll
                for (int mt = 0; mt < 2; mt++) {
                    mma16816f(acc[mt][nt], ah[mt], bh[nt]);
                    mma16816f(acc[mt][nt], ah[mt], bl[nt]);
                }
        }
        __syncthreads();
        buf ^= 1;
    }

#pragma unroll
    for (int mt = 0; mt < 2; mt++) {
        int r0 = row0 + wm*32 + mt*16 + (lane>>2);
#pragma unroll
        for (int nt = 0; nt < NTL; nt++) {
            int cc = wn*WN + nt*8 + (lane&3)*2;
            float b0 = s_bias[cc], b1 = s_bias[cc+1];
            float v0 = acc[mt][nt][0] + b0, v1 = acc[mt][nt][1] + b1;
            float v2 = acc[mt][nt][2] + b0, v3 = acc[mt][nt][3] + b1;
            if (MODE == 0) {
                *(float2*)&Cf[(size_t)r0 * Nc + col0 + cc]     = make_float2(v0, v1);
                *(float2*)&Cf[(size_t)(r0+8) * Nc + col0 + cc] = make_float2(v2, v3);
            } else {
                v0 = fmaxf(v0, 0.f); v1 = fmaxf(v1, 0.f);
                v2 = fmaxf(v2, 0.f); v3 = fmaxf(v3, 0.f);
                *(uint32_t*)&coH[(size_t)r0 * Nc + col0 + cc] =
                    (uint32_t)to_fp16(v0) | ((uint32_t)to_fp16(v1) << 16);
                *(uint32_t*)&coH[(size_t)(r0+8) * Nc + col0 + cc] =
                    (uint32_t)to_fp16(v2) | ((uint32_t)to_fp16(v3) << 16);
            }
        }
    }
}

// =================================================================================
// fp16 GEMM + bias + relu + masked segment-max epilogue (last layer).
// NOTE: s_bias must live BEYOND max(operand, red) region — red aliases dsm[0..).
// =================================================================================
template<int KC, int BN>
__global__ void __launch_bounds__(256, 2) hmax_pl(
    const ushort_t* __restrict__ aH,
    const ushort_t* __restrict__ bHi, const ushort_t* __restrict__ bLo,
    const float* __restrict__ bias, const int* __restrict__ cnt,
    float* __restrict__ out, int Nc, int Kn, int colOff, int rowBase)
{
    extern __shared__ char dsm[];
    constexpr int KP = 40;
    const uint32_t BH_OFF = (uint32_t)(2*128*KP*2);
    const uint32_t BL_OFF = BH_OFF + (uint32_t)(2*BN*KP*2);
    constexpr int OPB = (2*128*KP + 4*BN*KP) * 2;    // operand bytes
    constexpr int RDB = 128 * (BN + 1) * 4;          // reduction bytes
    float* s_bias = (float*)(dsm + (OPB > RDB ? OPB : RDB));   // past BOTH regions
    float* red    = (float*)dsm;

    const uint32_t base = smem_u32(dsm);

    const int tid  = threadIdx.x;
    const int row0 = rowBase + blockIdx.x * 128;
    const int col0 = blockIdx.y * BN;
    if (tid < BN) s_bias[tid] = bias[col0 + tid];

    const int lane = tid & 31, w = tid >> 5;
    const int wm = w & 3, wn = w >> 2;
    constexpr int WN  = BN / 2;
    constexpr int NTL = WN / 8;

    float acc[2][NTL][4];
#pragma unroll
    for (int mt = 0; mt < 2; mt++)
#pragma unroll
        for (int nt = 0; nt < NTL; nt++)
#pragma unroll
            for (int q = 0; q < 4; q++) acc[mt][nt][q] = 0.f;

    constexpr int NKB = KC / 32;

    auto load_stage = [&](int kb, int buf) {
        const int kk = kb * 32;
#pragma unroll
        for (int i = 0; i < 2; i++) {
            int c = tid * 2 + i;
            int row = c >> 2, kc = (c & 3) * 8;
            cpa16(base + (uint32_t)((buf * 128 * KP + row * KP + kc) * 2),
                  aH + (size_t)(row0 + row) * KC + kk + kc);
        }
#pragma unroll
        for (int i = 0; i < 2; i++) {
            int c = tid * 2 + i;
            int row = c >> 2, kc = (c & 3) * 8;
            uint32_t d = base + BH_OFF + (uint32_t)((buf * BN * KP + row * KP + kc) * 2);
            cpa16(d,                     bHi + (size_t)(col0 + row) * KC + kk + kc);
            cpa16(d + (BL_OFF - BH_OFF), bLo + (size_t)(col0 + row) * KC + kk + kc);
        }
    };

    const int g  = lane >> 3, lr = lane & 7;
    int aoff0[2], boff0[NTL/2];
#pragma unroll
    for (int mt = 0; mt < 2; mt++)
        aoff0[mt] = (wm*32 + mt*16 + (g & 1)*8 + lr) * KP + (g >> 1)*8;
#pragma unroll
    for (int p = 0; p < NTL/2; p++)
        boff0[p] = (wn*WN + p*16 + (g >> 1)*8 + lr) * KP + (g & 1)*8;

    load_stage(0, 0);
    CP_COMMIT();

    int buf = 0;
    for (int kb = 0; kb < NKB; kb++) {
        if (kb + 1 < NKB) { load_stage(kb + 1, buf ^ 1); CP_COMMIT(); CP_WAIT1(); }
        else              { CP_WAIT0(); }
        __syncthreads();

        const uint32_t aBuf = base + (uint32_t)(buf*128*KP*2);
        const uint32_t bBuf = base + BH_OFF + (uint32_t)(buf*BN*KP*2);
#pragma unroll
        for (int k2 = 0; k2 < 32; k2 += 16) {
            uint32_t ah[2][4];
#pragma unroll
            for (int mt = 0; mt < 2; mt++) {
                uint32_t ad = aBuf + (uint32_t)((aoff0[mt] + k2) * 2);
                LDSM4(ah[mt][0], ah[mt][1], ah[mt][2], ah[mt][3], ad);
            }
            uint32_t bh[NTL][2], bl[NTL][2];
#pragma unroll
            for (int p = 0; p < NTL/2; p++) {
                uint32_t bd = bBuf + (uint32_t)((boff0[p] + k2) * 2);
                LDSM4(bh[2*p][0], bh[2*p][1], bh[2*p+1][0], bh[2*p+1][1], bd);
                LDSM4(bl[2*p][0], bl[2*p][1], bl[2*p+1][0], bl[2*p+1][1],
                      bd + (BL_OFF - BH_OFF));
            }
#pragma unroll
            for (int nt = 0; nt < NTL; nt++)
#pragma unroll
                for (int mt = 0; mt < 2; mt++) {
                    mma16816f(acc[mt][nt], ah[mt], bh[nt]);
                    mma16816f(acc[mt][nt], ah[mt], bl[nt]);
                }
        }
        __syncthreads();
        buf ^= 1;
    }

#pragma unroll
    for (int mt = 0; mt < 2; mt++) {
        int lr2 = wm*32 + mt*16 + (lane>>2);
        int ok0 = (lr2 % Kn)     < cnt[(row0 + lr2) / Kn];
        int ok1 = ((lr2+8) % Kn) < cnt[(row0 + lr2 + 8) / Kn];
#pragma unroll
        for (int nt = 0; nt < NTL; nt++) {
            int cc = wn*WN + nt*8 + (lane&3)*2;
            float b0 = s_bias[cc], b1 = s_bias[cc+1];
            float v0 = fmaxf(acc[mt][nt][0] + b0, 0.f);
            float v1 = fmaxf(acc[mt][nt][1] + b1, 0.f);
            float v2 = fmaxf(acc[mt][nt][2] + b0, 0.f);
            float v3 = fmaxf(acc[mt][nt][3] + b1, 0.f);
            red[(size_t)lr2*(BN+1) + cc]         = ok0 ? v0 : -INF_F;
            red[(size_t)lr2*(BN+1) + cc + 1]     = ok0 ? v1 : -INF_F;
            red[(size_t)(lr2+8)*(BN+1) + cc]     = ok1 ? v2 : -INF_F;
            red[(size_t)(lr2+8)*(BN+1) + cc + 1] = ok1 ? v3 : -INF_F;
        }
    }
    __syncthreads();

    const int nseg = 128 / Kn;
    const int cb   = row0 / Kn;
    for (int o = tid; o < nseg * BN; o += 256) {
        int seg = o / BN, col = o % BN;
        float m = -INF_F;
        int rb = seg * Kn;
        for (int r = 0; r < Kn; r++)
            m = fmaxf(m, red[(size_t)(rb + r)*(BN+1) + col]);
        out[(size_t)(cb + seg) * 640 + colOff + col0 + col] = m;
    }
}

// =================================================================================
// 1) Farthest point sampling — single barrier/step (bitwise-frozen math)
// =================================================================================
__global__ void __launch_bounds__(1024) fps_kernel(const float* __restrict__ pos)
{
    const int b    = blockIdx.x;
    const int tid  = threadIdx.x;
    const int lane = tid & 31, wid = tid >> 5;
    const float* p = pos + (size_t)b * NN * 3;

    __shared__ float s_xyz[NN*3];
    __shared__ float s_v[2][32];
    __shared__ int   s_i[2][32];

    for (int i = tid; i < NN*3; i += 1024) s_xyz[i] = p[i];

    float px[4], py[4], pz[4], md[4];
#pragma unroll
    for (int i = 0; i < 4; i++) {
        int j = tid * 4 + i;
        px[i] = p[j*3+0]; py[i] = p[j*3+1]; pz[i] = p[j*3+2];
        md[i] = INF_F;
    }

    float cx = p[0], cy = p[1], cz = p[2];
    if (tid == 0) {
        size_t o = (size_t)b * SS * 3;
        g_centers[o] = cx; g_centers[o+1] = cy; g_centers[o+2] = cz;
    }
    __syncthreads();

    int par = 0;
    for (int s = 1; s < SS; s++) {
        float bv = -1.0f; int bi = 0;
#pragma unroll
        for (int i = 0; i < 4; i++) {
            float dx = __fsub_rn(px[i], cx);
            float dy = __fsub_rn(py[i], cy);
            float dz = __fsub_rn(pz[i], cz);
            float d2 = __fadd_rn(__fadd_rn(__fmul_rn(dx,dx), __fmul_rn(dy,dy)),
                                 __fmul_rn(dz,dz));
            md[i] = fminf(md[i], d2);
            if (md[i] > bv) { bv = md[i]; bi = tid*4 + i; }
        }
        unsigned ubv  = __float_as_uint(bv);
        unsigned wmax = __reduce_max_sync(0xffffffffu, ubv);
        unsigned ball = __ballot_sync(0xffffffffu, ubv == wmax);
        int src = __ffs(ball) - 1;
        int wbi = __shfl_sync(0xffffffffu, bi, src);
        if (lane == 0) { s_v[par][wid] = __uint_as_float(wmax); s_i[par][wid] = wbi; }
        __syncthreads();

        unsigned v  = __float_as_uint(s_v[par][lane]);
        int      iv = s_i[par][lane];
        unsigned m2 = __reduce_max_sync(0xffffffffu, v);
        unsigned ba = __ballot_sync(0xffffffffu, v == m2);
        int sc = __ffs(ba) - 1;
        int i2 = __shfl_sync(0xffffffffu, iv, sc);

        cx = s_xyz[i2*3+0]; cy = s_xyz[i2*3+1]; cz = s_xyz[i2*3+2];
        if (tid == 0) {
            size_t o = ((size_t)b*SS + s) * 3;
            g_centers[o] = cx; g_centers[o+1] = cy; g_centers[o+2] = cz;
        }
        par ^= 1;
    }
}

// =================================================================================
// 2) Radius ball query + exact top-K (per-scale output pointers)
// =================================================================================
__global__ void __launch_bounds__(256) nbr_kernel(const float* __restrict__ pos,
                                                  float r2, int Kn,
                                                  int* __restrict__ nbrOut,
                                                  int* __restrict__ cntOut)
{
    __shared__ unsigned long long keys[4096];
    __shared__ int s_count;
    const int ci  = blockIdx.x;
    const int b   = ci / SS;
    const int tid = threadIdx.x;
    if (tid == 0) s_count = 0;
    __syncthreads();

    const float cx = g_centers[ci*3+0], cy = g_centers[ci*3+1], cz = g_centers[ci*3+2];
    const float* p = pos + (size_t)b * NN * 3;

    for (int j = tid; j < NN; j += 256) {
        float dx = __fsub_rn(cx, p[j*3+0]);
        float dy = __fsub_rn(cy, p[j*3+1]);
        float dz = __fsub_rn(cz, p[j*3+2]);
        float d2 = __fadd_rn(__fadd_rn(__fmul_rn(dx,dx), __fmul_rn(dy,dy)),
                             __fmul_rn(dz,dz));
        if (d2 <= r2) {
            int w = atomicAdd(&s_count, 1);
            keys[w] = (((unsigned long long)__float_as_uint(d2)) << 32) | (unsigned)j;
        }
    }
    __syncthreads();
    const int M = s_count;
    int n = 16;
    while (n < M || n < Kn) n <<= 1;
    for (int i = M + tid; i < n; i += 256) keys[i] = 0xFFFFFFFFFFFFFFFFULL;
    __syncthreads();

    for (int size = 2; size <= n; size <<= 1) {
        for (int stride = size >> 1; stride > 0; stride >>= 1) {
            for (int i = tid; i < (n >> 1); i += 256) {
                int p0 = 2*i - (i & (stride - 1));
                int p1 = p0 + stride;
                unsigned long long a = keys[p0], c = keys[p1];
                bool asc = ((p0 & size) == 0);
                if (asc ? (a > c) : (a < c)) { keys[p0] = c; keys[p1] = a; }
            }
            __syncthreads();
        }
    }

    for (int k = tid; k < Kn; k += 256) {
        int j = (k < M) ? (int)(keys[k] & 0xFFFFFFFFu) : 0;
        nbrOut[(size_t)ci * Kn + k] = b * NN + j;
    }
    if (tid == 0) cntOut[ci] = (M < Kn) ? M : Kn;
}

// =================================================================================
// 3) Fused gather + layer-1 (emits h1 fp16 single plane; per-scale nbr pointer)
// =================================================================================
__global__ void __launch_bounds__(256) fused_l1(const float* __restrict__ pos,
                                                const float* __restrict__ xwb,
                                                const float* __restrict__ W1,
                                                int Kn, int c1,
                                                const int* __restrict__ nbr,
                                                ushort_t* __restrict__ hH)
{
    __shared__ float s_wp[3*128];
    const int tid  = threadIdx.x;
    for (int i = tid; i < 3 * c1; i += 256)
        s_wp[i] = W1[(size_t)(64 + i / c1) * c1 + (i % c1)];
    __syncthreads();

    const int warp = tid >> 5, lane = tid & 31;
    const long row = (long)blockIdx.x * 8 + warp;
    const int  ci  = (int)(row / Kn);
    const int  j   = nbr[row];

    const float p0 = __fsub_rn(pos[(size_t)j*3+0], g_centers[(size_t)ci*3+0]);
    const float p1 = __fsub_rn(pos[(size_t)j*3+1], g_centers[(size_t)ci*3+1]);
    const float p2 = __fsub_rn(pos[(size_t)j*3+2], g_centers[(size_t)ci*3+2]);

    const float* xr = xwb + (size_t)j * c1;
    const size_t rb = (size_t)row * c1;
#pragma unroll 2
    for (int it = 0; it < c1/64; it++) {
        int cc = lane*2 + it*64;
        float v0 = xr[cc], v1 = xr[cc+1];
        v0 = fmaf(p0, s_wp[cc],          v0);
        v0 = fmaf(p1, s_wp[c1 + cc],     v0);
        v0 = fmaf(p2, s_wp[2*c1 + cc],   v0);
        v1 = fmaf(p0, s_wp[cc+1],        v1);
        v1 = fmaf(p1, s_wp[c1 + cc+1],   v1);
        v1 = fmaf(p2, s_wp[2*c1 + cc+1], v1);
        v0 = fmaxf(v0, 0.f); v1 = fmaxf(v1, 0.f);
        *(uint32_t*)&hH[rb + cc] = (uint32_t)to_fp16(v0) | ((uint32_t)to_fp16(v1) << 16);
    }
}

// =================================================================================
// 4) new_pos / new_batch tail
// =================================================================================
__global__ void tail_kernel(float* __restrict__ out, int writePos, int writeBatch)
{
    int i = blockIdx.x * blockDim.x + threadIdx.x;
    if (i >= NC) return;
    if (writePos) {
        out[OUT_POS_OFF + i*3 + 0] = g_centers[i*3+0];
        out[OUT_POS_OFF + i*3 + 1] = g_centers[i*3+1];
        out[OUT_POS_OFF + i*3 + 2] = g_centers[i*3+2];
    }
    if (writeBatch) out[OUT_BATCH_OFF + i] = (float)(i / SS);
}

// =================================================================================
static inline int smem_pl(int BN) { return 160 * (128 + 2*BN) + 512; }
static inline int smem_mx(int BN) {
    int op = 160 * (128 + 2*BN);
    int rd = 128 * (BN + 1) * 4;
    return (op > rd ? op : rd) + 512;
}

extern "C" void kernel_launch(void* const* d_in, const int* in_sizes, int n_in,
                              void* d_out, int out_size)
{
    const float* x   = (const float*)d_in[0];
    const float* pos = (const float*)d_in[1];
    const float* W[3][3];
    const float* bv[3][3];
    int ii = 3;
    for (int s = 0; s < 3; s++)
        for (int l = 0; l < 3; l++) {
            W[s][l]  = (const float*)d_in[ii++];
            bv[s][l] = (const float*)d_in[ii++];
        }
    float* out = (float*)d_out;

    void *pX = nullptr, *pXP = nullptr, *pWP = nullptr, *pH1 = nullptr, *pH2 = nullptr;
    void *pNB = nullptr, *pCT = nullptr;
    cudaGetSymbolAddress(&pX, g_xw);
    cudaGetSymbolAddress(&pXP, g_xpl);
    cudaGetSymbolAddress(&pWP, g_wpl);
    cudaGetSymbolAddress(&pH1, g_h1);
    cudaGetSymbolAddress(&pH2, g_h2);
    cudaGetSymbolAddress(&pNB, g_nbr);
    cudaGetSymbolAddress(&pCT, g_cnt);
    float*    xw   = (float*)pX;
    ushort_t* xpl  = (ushort_t*)pXP;
    ushort_t* wpl  = (ushort_t*)pWP;
    ushort_t* h1b  = (ushort_t*)pH1;
    ushort_t* h2b  = (ushort_t*)pH2;
    int*      nbrb = (int*)pNB;
    int*      cntb = (int*)pCT;

    cudaFuncSetAttribute(hgemm_pl<64,64,0>,   cudaFuncAttributeMaxDynamicSharedMemorySize, smem_pl(64));
    cudaFuncSetAttribute(hgemm_pl<64,128,0>,  cudaFuncAttributeMaxDynamicSharedMemorySize, smem_pl(128));
    cudaFuncSetAttribute(hgemm_pl<64,64,1>,   cudaFuncAttributeMaxDynamicSharedMemorySize, smem_pl(64));
    cudaFuncSetAttribute(hgemm_pl<128,128,1>, cudaFuncAttributeMaxDynamicSharedMemorySize, smem_pl(128));
    cudaFuncSetAttribute(hmax_pl<64,128>,     cudaFuncAttributeMaxDynamicSharedMemorySize, smem_mx(128));
    cudaFuncSetAttribute(hmax_pl<128,128>,    cudaFuncAttributeMaxDynamicSharedMemorySize, smem_mx(128));

    const int    Kl[3]    = {16, 32, 64};
    const float  r2l[3]   = {(float)(0.1*0.1), (float)(0.2*0.2), (float)(0.4*0.4)};
    const int    c1[3]    = {64, 128, 128};
    const int    coff[3]  = {0, 128, 384};
    const size_t xwOff[3] = {0, (size_t)NPTS*64, (size_t)NPTS*(64+128)};
    const size_t E[3]  = {(size_t)NC*16*64, (size_t)NC*32*128, (size_t)NC*64*128};
    const size_t hO[3] = {0, E[0], E[0] + E[1]};
    const size_t nbrOff[3] = {0, (size_t)NC*16, (size_t)NC*(16+32)};

    size_t woff = 0;
    size_t wxO[3], w2O[3], w3O[3], wxS[3], w2S[3], w3S[3];
    for (int s = 0; s < 3; s++) {
        wxS[s] = (size_t)64 * c1[s];    wxO[s] = woff; woff += 2*wxS[s];
        w2S[s] = (size_t)c1[s] * (s ? 128 : 64); w2O[s] = woff; woff += 2*w2S[s];
        w3S[s] = (size_t)(s ? 128 : 64) * (s ? 256 : 128); w3O[s] = woff; woff += 2*w3S[s];
    }

    // ---- 2-stream envelope (proven R9/R12-R14) ----------------------------------
    cudaStream_t s2;
    cudaStreamCreateWithFlags(&s2, cudaStreamNonBlocking);
    cudaEvent_t evFork, evCent, evXw0, evXw2, evL12, evTail;
    cudaEventCreateWithFlags(&evFork, cudaEventDisableTiming);
    cudaEventCreateWithFlags(&evCent, cudaEventDisableTiming);
    cudaEventCreateWithFlags(&evXw0,  cudaEventDisableTiming);
    cudaEventCreateWithFlags(&evXw2,  cudaEventDisableTiming);
    cudaEventCreateWithFlags(&evL12,  cudaEventDisableTiming);
    cudaEventCreateWithFlags(&evTail, cudaEventDisableTiming);

    cudaEventRecord(evFork, 0);
    cudaStreamWaitEvent(s2, evFork, 0);

    // side stream: fps
    fps_kernel<<<BB, 1024, 0, s2>>>(pos);
    cudaEventRecord(evCent, s2);

    // main stream: conversions + xw GEMMs
    xconv<<<(int)(((size_t)NPTS*64 + 255)/256), 256>>>(x, xpl);
    for (int s = 0; s < 3; s++) {
        const int c2v = s ? 128 : 64, c3v = s ? 256 : 128;
        wconv<<<(int)((wxS[s]+255)/256), 256>>>(W[s][0], c1[s], 0, 64, c1[s],
                                                wpl + wxO[s], wpl + wxO[s] + wxS[s]);
        wconv<<<(int)((w2S[s]+255)/256), 256>>>(W[s][1], c2v, 0, c1[s], c2v,
                                                wpl + w2O[s], wpl + w2O[s] + w2S[s]);
        wconv<<<(int)((w3S[s]+255)/256), 256>>>(W[s][2], c3v, 0, c2v, c3v,
                                                wpl + w3O[s], wpl + w3O[s] + w3S[s]);
    }
    hgemm_pl<64,64,0><<<dim3(NPTS/128,1), 256, smem_pl(64)>>>(
        xpl, wpl + wxO[0], wpl + wxO[0] + wxS[0],
        bv[0][0], xw + xwOff[0], nullptr, 64, 0);
    cudaEventRecord(evXw0, 0);
    hgemm_pl<64,128,0><<<dim3(NPTS/128,1), 256, smem_pl(128)>>>(
        xpl, wpl + wxO[1], wpl + wxO[1] + wxS[1],
        bv[1][0], xw + xwOff[1], nullptr, 128, 0);
    hgemm_pl<64,128,0><<<dim3(NPTS/128,1), 256, smem_pl(128)>>>(
        xpl, wpl + wxO[2], wpl + wxO[2] + wxS[2],
        bv[2][0], xw + xwOff[2], nullptr, 128, 0);
    cudaEventRecord(evXw2, 0);

    // --- pointer sets ---
    ushort_t* h1p0 = h1b + hO[0]; ushort_t* h2p0 = h2b + hO[0];
    ushort_t* h1p1 = h1b + hO[1]; ushort_t* h2p1 = h2b + hO[1];
    ushort_t* h1p2 = h1b + hO[2]; ushort_t* h2p2 = h2b + hO[2];
    const int R2 = NC * Kl[2];
    const int R2H = R2 / 2;

    // side stream: nbr0, nbr2, s0 chain, l1_2, s2 lo-half chain, tail
    {
        const int K = Kl[0], R = NC * K;
        nbr_kernel<<<NC, 256, 0, s2>>>(pos, r2l[0], K, nbrb + nbrOff[0], cntb);
        nbr_kernel<<<NC, 256, 0, s2>>>(pos, r2l[2], Kl[2],
                                       nbrb + nbrOff[2], cntb + 2*NC);

        cudaStreamWaitEvent(s2, evXw0, 0);
        fused_l1<<<R/8, 256, 0, s2>>>(pos, xw + xwOff[0], W[0][0], K, c1[0],
                                      nbrb + nbrOff[0], h1p0);
        hgemm_pl<64,64,1><<<dim3(R/128,1), 256, smem_pl(64), s2>>>(
            h1p0, wpl + w2O[0], wpl + w2O[0] + w2S[0],
            bv[0][1], nullptr, h2p0, 64, 0);
        hmax_pl<64,128><<<dim3(R/128,1), 256, smem_mx(128), s2>>>(
            h2p0, wpl + w3O[0], wpl + w3O[0] + w3S[0],
            bv[0][2], cntb, out, 128, K, coff[0], 0);

        cudaStreamWaitEvent(s2, evXw2, 0);
        fused_l1<<<R2/8, 256, 0, s2>>>(pos, xw + xwOff[2], W[2][0], Kl[2], c1[2],
                                       nbrb + nbrOff[2], h1p2);
        cudaEventRecord(evL12, s2);

        hgemm_pl<128,128,1><<<dim3(R2H/128,1), 256, smem_pl(128), s2>>>(
            h1p2, wpl + w2O[2], wpl + w2O[2] + w2S[2],
            bv[2][1], nullptr, h2p2, 128, 0);
        hmax_pl<128,128><<<dim3(R2H/128,2), 256, smem_mx(128), s2>>>(
            h2p2, wpl + w3O[2], wpl + w3O[2] + w3S[2],
            bv[2][2], cntb + 2*NC, out, 256, Kl[2], coff[2], 0);

        const int writePos   = (out_size >= OUT_POS_OFF + NC*3);
        const int writeBatch = (out_size >= OUT_BATCH_OFF + NC);
        tail_kernel<<<(NC + 255)/256, 256, 0, s2>>>(out, writePos, writeBatch);
        cudaEventRecord(evTail, s2);
    }

    // main stream: scale 1 full chain, then s2 hi-half
    cudaStreamWaitEvent(0, evCent, 0);
    {
        const int s = 1, K = Kl[1], R = NC * K;
        nbr_kernel<<<NC, 256>>>(pos, r2l[s], K, nbrb + nbrOff[s], cntb + NC);
        fused_l1<<<R/8, 256>>>(pos, xw + xwOff[s], W[s][0], K, c1[s],
                               nbrb + nbrOff[s], h1p1);
        hgemm_pl<128,128,1><<<dim3(R/128,1), 256, smem_pl(128)>>>(
            h1p1, wpl + w2O[s], wpl + w2O[s] + w2S[s],
            bv[s][1], nullptr, h2p1, 128, 0);
        hmax_pl<128,128><<<dim3(R/128,2), 256, smem_mx(128)>>>(
            h2p1, wpl + w3O[s], wpl + w3O[s] + w3S[s],
            bv[s][2], cntb + NC, out, 256, K, coff[s], 0);
    }
    cudaStreamWaitEvent(0, evL12, 0);
    {
        hgemm_pl<128,128,1><<<dim3(R2H/128,1), 256, smem_pl(128)>>>(
            h1p2, wpl + w2O[2], wpl + w2O[2] + w2S[2],
            bv[2][1], nullptr, h2p2, 128, R2H);
        hmax_pl<128,128><<<dim3(R2H/128,2), 256, smem_mx(128)>>>(
            h2p2, wpl + w3O[2], wpl + w3O[2] + w3S[2],
            bv[2][2], cntb + 2*NC, out, 256, Kl[2], coff[2], R2H);
    }

    // final join
    cudaStreamWaitEvent(0, evTail, 0);
}